// round 2
// baseline (speedup 1.0000x reference)
#include <cuda_runtime.h>

// Problem: AttentionHead  B=16, S=1024, H=1024, D=128
// out[b,s,d] = softmax_t( (q·k^T + q·k_bias) / sqrt(D) ) @ (v, v_bias)

constexpr int Bsz = 16;
constexpr int Sq  = 1024;
constexpr int Hd  = 1024;
constexpr int Dd  = 128;

// Scratch (static __device__ arrays; no runtime allocation allowed)
__device__ float g_q[Bsz * Sq * Dd];                 // 8 MB
__device__ float g_k[Bsz * Sq * Dd];                 // 8 MB
__device__ float g_v[Bsz * Sq * Dd];                 // 8 MB
__device__ float g_scores[(size_t)Bsz * Sq * Sq];    // 64 MB

// ---------------------------------------------------------------------------
// Generic tiled SGEMM:  C[M,N] = A[M,K] * op(B) (+ bias) (+= if ACCUM)
//   B_TRANS=true :  B is [N,K] row-major (C = A * B^T)  -- both K-contiguous
//   B_TRANS=false:  B is [K,N] row-major (C = A * B)
// Block tile 128x128, BK=16, 256 threads, 8x8 per-thread micro-tile.
// Requires M%128==0, N%128==0, K%16==0 (true for all uses here).
// ---------------------------------------------------------------------------
constexpr int BM = 128, BN = 128, BK = 16;

template <bool B_TRANS, bool ACCUM, bool BIAS>
__global__ __launch_bounds__(256)
void sgemm_kernel(const float* __restrict__ A, const float* __restrict__ Bm,
                  const float* __restrict__ bias, float* __restrict__ C,
                  int M, int N, int K,
                  long long sA, long long sB, long long sC)
{
    __shared__ float As[BK][BM + 4];
    __shared__ float Bs[BK][BN + 4];

    const int bn0 = blockIdx.x * BN;
    const int bm0 = blockIdx.y * BM;
    const float* Ab = A + (long long)blockIdx.z * sA;
    const float* Bb = Bm + (long long)blockIdx.z * sB;
    float*       Cb = C + (long long)blockIdx.z * sC;

    const int tid = threadIdx.x;
    const int tx  = tid & 15;   // 16 column groups
    const int ty  = tid >> 4;   // 16 row groups

    float acc[8][8];
#pragma unroll
    for (int i = 0; i < 8; ++i)
#pragma unroll
        for (int j = 0; j < 8; ++j) acc[i][j] = 0.f;

    for (int k0 = 0; k0 < K; k0 += BK) {
        // ---- load A tile (BMxBK), store transposed As[k][m] ----
#pragma unroll
        for (int i = 0; i < 2; ++i) {
            int f  = tid + i * 256;          // float4 index in [0,512)
            int m  = f >> 2;                 // 0..127
            int kq = (f & 3) << 2;           // 0,4,8,12
            float4 v = *reinterpret_cast<const float4*>(
                &Ab[(long long)(bm0 + m) * K + k0 + kq]);
            As[kq + 0][m] = v.x; As[kq + 1][m] = v.y;
            As[kq + 2][m] = v.z; As[kq + 3][m] = v.w;
        }
        // ---- load B tile ----
        if (B_TRANS) {
#pragma unroll
            for (int i = 0; i < 2; ++i) {
                int f  = tid + i * 256;
                int n  = f >> 2;
                int kq = (f & 3) << 2;
                float4 v = *reinterpret_cast<const float4*>(
                    &Bb[(long long)(bn0 + n) * K + k0 + kq]);
                Bs[kq + 0][n] = v.x; Bs[kq + 1][n] = v.y;
                Bs[kq + 2][n] = v.z; Bs[kq + 3][n] = v.w;
            }
        } else {
#pragma unroll
            for (int i = 0; i < 2; ++i) {
                int f = tid + i * 256;
                int k = f >> 5;              // 0..15
                int n = (f & 31) << 2;       // 0..124
                float4 v = *reinterpret_cast<const float4*>(
                    &Bb[(long long)(k0 + k) * N + bn0 + n]);
                *reinterpret_cast<float4*>(&Bs[k][n]) = v;
            }
        }
        __syncthreads();

#pragma unroll
        for (int k = 0; k < BK; ++k) {
            float ar[8], br[8];
            *reinterpret_cast<float4*>(&ar[0]) =
                *reinterpret_cast<const float4*>(&As[k][ty * 8]);
            *reinterpret_cast<float4*>(&ar[4]) =
                *reinterpret_cast<const float4*>(&As[k][ty * 8 + 4]);
            // column interleave: cols tx*4..tx*4+3 and 64+tx*4..+3 (bank-conflict free)
            *reinterpret_cast<float4*>(&br[0]) =
                *reinterpret_cast<const float4*>(&Bs[k][tx * 4]);
            *reinterpret_cast<float4*>(&br[4]) =
                *reinterpret_cast<const float4*>(&Bs[k][64 + tx * 4]);
#pragma unroll
            for (int i = 0; i < 8; ++i)
#pragma unroll
                for (int j = 0; j < 8; ++j) acc[i][j] += ar[i] * br[j];
        }
        __syncthreads();
    }

#pragma unroll
    for (int i = 0; i < 8; ++i) {
        int m = bm0 + ty * 8 + i;
#pragma unroll
        for (int half = 0; half < 2; ++half) {
            int n = bn0 + half * 64 + tx * 4;
            float4 val;
            val.x = acc[i][half * 4 + 0]; val.y = acc[i][half * 4 + 1];
            val.z = acc[i][half * 4 + 2]; val.w = acc[i][half * 4 + 3];
            if (BIAS) {
                float4 bv4 = *reinterpret_cast<const float4*>(&bias[n]);
                val.x += bv4.x; val.y += bv4.y; val.z += bv4.z; val.w += bv4.w;
            }
            float* cp = &Cb[(long long)m * N + n];
            if (ACCUM) {
                float4 old = *reinterpret_cast<const float4*>(cp);
                val.x += old.x; val.y += old.y; val.z += old.z; val.w += old.w;
            }
            *reinterpret_cast<float4*>(cp) = val;
        }
    }
}

// ---------------------------------------------------------------------------
// attn2 + scale + mask:  scores[b,s,t] = (scores[b,s,t] + q[b,s,:]·k_bias[s,t,:]) * scale
// Block = (s, t-tile of 256). k_bias read exactly once (all 16 batches share it).
// ---------------------------------------------------------------------------
__global__ __launch_bounds__(256)
void attn2_kernel(const float* __restrict__ q, const float* __restrict__ kb,
                  const int* __restrict__ mask, float* __restrict__ scores)
{
    const int s = blockIdx.x;
    const int t = blockIdx.y * 256 + threadIdx.x;
    __shared__ float qs[16][128];   // q[:, s, :]
#pragma unroll
    for (int i = 0; i < 2; ++i) {
        int f  = threadIdx.x + i * 256;   // float4 idx in [0,512)
        int b  = f >> 5;
        int d4 = (f & 31) << 2;
        *reinterpret_cast<float4*>(&qs[b][d4]) =
            *reinterpret_cast<const float4*>(&q[((long long)b * Sq + s) * Dd + d4]);
    }
    __syncthreads();

    float acc[16];
#pragma unroll
    for (int b = 0; b < 16; ++b) acc[b] = 0.f;

    const float4* kb4 = reinterpret_cast<const float4*>(&kb[((long long)s * Sq + t) * Dd]);
#pragma unroll 8
    for (int dv = 0; dv < 32; ++dv) {
        float4 kv = kb4[dv];
        int d = dv << 2;
#pragma unroll
        for (int b = 0; b < 16; ++b) {
            float4 qv = *reinterpret_cast<const float4*>(&qs[b][d]);
            acc[b] += qv.x * kv.x + qv.y * kv.y + qv.z * kv.z + qv.w * kv.w;
        }
    }

    const float scale = 0.08838834764831845f;  // 1/sqrt(128)
#pragma unroll
    for (int b = 0; b < 16; ++b) {
        long long idx = ((long long)b * Sq + s) * (long long)Sq + t;
        float sc = (scores[idx] + acc[b]) * scale;
        if (mask[b * Sq + t] == 0) sc = -1e9f;
        scores[idx] = sc;
    }
}

// ---------------------------------------------------------------------------
// Row softmax over t (row length 1024), block per row, 256 threads x float4.
// ---------------------------------------------------------------------------
__global__ __launch_bounds__(256)
void softmax_kernel(float* __restrict__ scores)
{
    long long row = blockIdx.x;
    float* p = scores + row * Sq;
    int tid = threadIdx.x;
    float4 x = *reinterpret_cast<const float4*>(&p[tid << 2]);

    float m = fmaxf(fmaxf(x.x, x.y), fmaxf(x.z, x.w));
    __shared__ float red[8];
#pragma unroll
    for (int o = 16; o > 0; o >>= 1) m = fmaxf(m, __shfl_xor_sync(0xffffffffu, m, o));
    if ((tid & 31) == 0) red[tid >> 5] = m;
    __syncthreads();
    float M = red[0];
#pragma unroll
    for (int i = 1; i < 8; ++i) M = fmaxf(M, red[i]);

    float e0 = __expf(x.x - M), e1 = __expf(x.y - M);
    float e2 = __expf(x.z - M), e3 = __expf(x.w - M);
    float ssum = e0 + e1 + e2 + e3;
#pragma unroll
    for (int o = 16; o > 0; o >>= 1) ssum += __shfl_xor_sync(0xffffffffu, ssum, o);
    __syncthreads();
    if ((tid & 31) == 0) red[tid >> 5] = ssum;
    __syncthreads();
    float Ssum = 0.f;
#pragma unroll
    for (int i = 0; i < 8; ++i) Ssum += red[i];
    float inv = 1.0f / Ssum;

    float4 o4 = {e0 * inv, e1 * inv, e2 * inv, e3 * inv};
    *reinterpret_cast<float4*>(&p[tid << 2]) = o4;
}

// ---------------------------------------------------------------------------
// values2: out[b,s,d] = sum_t w[b,s,t] * v_bias[s,t,d]  (writes out, beta=0)
// Block per s; v_bias read exactly once. thread -> (b = tid/16, d-cols tid%16*4 and +64)
// ---------------------------------------------------------------------------
__global__ __launch_bounds__(256)
void values2_kernel(const float* __restrict__ w, const float* __restrict__ vb,
                    float* __restrict__ out)
{
    const int s = blockIdx.x;
    __shared__ float vbs[32][128];
    __shared__ float ws[16][33];
    const int tid = threadIdx.x;
    const int b = tid >> 4;            // 0..15
    const int c = (tid & 15) << 2;     // 0,4,...,60

    float acc[8] = {0, 0, 0, 0, 0, 0, 0, 0};
    for (int t0 = 0; t0 < Sq; t0 += 32) {
#pragma unroll
        for (int i = 0; i < 4; ++i) {
            int f  = tid + i * 256;        // float4 idx in [0,1024)
            int tt = f >> 5;
            int dd = (f & 31) << 2;
            *reinterpret_cast<float4*>(&vbs[tt][dd]) =
                *reinterpret_cast<const float4*>(&vb[((long long)s * Sq + t0 + tt) * Dd + dd]);
        }
#pragma unroll
        for (int i = 0; i < 2; ++i) {
            int g = tid + i * 256;
            int bb = g >> 5, tt = g & 31;
            ws[bb][tt] = w[((long long)bb * Sq + s) * (long long)Sq + t0 + tt];
        }
        __syncthreads();
#pragma unroll
        for (int tt = 0; tt < 32; ++tt) {
            float wv = ws[b][tt];
            float4 v0 = *reinterpret_cast<const float4*>(&vbs[tt][c]);
            float4 v1 = *reinterpret_cast<const float4*>(&vbs[tt][c + 64]);
            acc[0] += wv * v0.x; acc[1] += wv * v0.y;
            acc[2] += wv * v0.z; acc[3] += wv * v0.w;
            acc[4] += wv * v1.x; acc[5] += wv * v1.y;
            acc[6] += wv * v1.z; acc[7] += wv * v1.w;
        }
        __syncthreads();
    }
    float4 o0 = {acc[0], acc[1], acc[2], acc[3]};
    float4 o1 = {acc[4], acc[5], acc[6], acc[7]};
    float* op = &out[((long long)b * Sq + s) * Dd];
    *reinterpret_cast<float4*>(&op[c])      = o0;
    *reinterpret_cast<float4*>(&op[c + 64]) = o1;
}

// ---------------------------------------------------------------------------
extern "C" void kernel_launch(void* const* d_in, const int* in_sizes, int n_in,
                              void* d_out, int out_size)
{
    const float* query  = (const float*)d_in[0];
    const float* key_   = (const float*)d_in[1];
    const float* value  = (const float*)d_in[2];
    const int*   mask   = (const int*)  d_in[3];
    const float* Wq     = (const float*)d_in[4];
    const float* bq     = (const float*)d_in[5];
    const float* Wk     = (const float*)d_in[6];
    const float* bk     = (const float*)d_in[7];
    const float* Wv     = (const float*)d_in[8];
    const float* bv     = (const float*)d_in[9];
    const float* k_bias = (const float*)d_in[10];
    const float* v_bias = (const float*)d_in[11];
    float* out = (float*)d_out;

    void *pq, *pk, *pv, *ps;
    cudaGetSymbolAddress(&pq, g_q);
    cudaGetSymbolAddress(&pk, g_k);
    cudaGetSymbolAddress(&pv, g_v);
    cudaGetSymbolAddress(&ps, g_scores);
    float* q  = (float*)pq;
    float* k  = (float*)pk;
    float* v  = (float*)pv;
    float* sc = (float*)ps;

    dim3 blk(256);

    // Projections: [16384,1024] x [128,1024]^T + bias
    dim3 gproj(1, (Bsz * Sq) / BM, 1);
    sgemm_kernel<true, false, true><<<gproj, blk>>>(query, Wq, bq, q, Bsz * Sq, Dd, Hd, 0, 0, 0);
    sgemm_kernel<true, false, true><<<gproj, blk>>>(key_,  Wk, bk, k, Bsz * Sq, Dd, Hd, 0, 0, 0);
    sgemm_kernel<true, false, true><<<gproj, blk>>>(value, Wv, bv, v, Bsz * Sq, Dd, Hd, 0, 0, 0);

    // attn1: scores[b] = q[b] (1024x128) * k[b]^T  (write)
    dim3 g2(Sq / BN, Sq / BM, Bsz);
    sgemm_kernel<true, false, false><<<g2, blk>>>(q, k, nullptr, sc, Sq, Sq, Dd,
        (long long)Sq * Dd, (long long)Sq * Dd, (long long)Sq * Sq);

    // attn2 + scale + mask  (k_bias read once)
    attn2_kernel<<<dim3(Sq, Sq / 256), blk>>>(q, k_bias, mask, sc);

    // softmax over t
    softmax_kernel<<<Bsz * Sq, blk>>>(sc);

    // values2: out = w @ v_bias (per s)   (v_bias read once)
    values2_kernel<<<Sq, blk>>>(sc, v_bias, out);

    // values1: out += w[b] (1024x1024) * v[b] (1024x128)
    dim3 g6(Dd / BN, Sq / BM, Bsz);
    sgemm_kernel<false, true, false><<<g6, blk>>>(sc, v, nullptr, out, Sq, Dd, Sq,
        (long long)Sq * Sq, (long long)Sq * Dd, (long long)Sq * Dd);
}

// round 3
// speedup vs baseline: 1.0044x; 1.0044x over previous
#include <cuda_runtime.h>

// Problem: AttentionHead  B=16, S=1024, H=1024, D=128
// out[b,s,d] = softmax_t( (q·k^T + q·k_bias) / sqrt(D) ) @ (v, v_bias)

constexpr int Bsz = 16;
constexpr int Sq  = 1024;
constexpr int Hd  = 1024;
constexpr int Dd  = 128;

// Scratch (static __device__ arrays; no runtime allocation allowed)
__device__ float g_q[Bsz * Sq * Dd];                 // 8 MB
__device__ float g_k[Bsz * Sq * Dd];                 // 8 MB
__device__ float g_v[Bsz * Sq * Dd];                 // 8 MB
__device__ float g_scores[(size_t)Bsz * Sq * Sq];    // 64 MB

// ---------------------------------------------------------------------------
// Generic tiled SGEMM:  C[M,N] = A[M,K] * op(B) (+ bias) (+= if ACCUM)
//   B_TRANS=true :  B is [N,K] row-major (C = A * B^T)  -- both K-contiguous
//   B_TRANS=false:  B is [K,N] row-major (C = A * B)
// Block tile 128x128, BK=16, 256 threads, 8x8 per-thread micro-tile.
// Requires M%128==0, N%128==0, K%16==0 (true for all uses here).
// ---------------------------------------------------------------------------
constexpr int BM = 128, BN = 128, BK = 16;

template <bool B_TRANS, bool ACCUM, bool BIAS>
__global__ __launch_bounds__(256)
void sgemm_kernel(const float* __restrict__ A, const float* __restrict__ Bm,
                  const float* __restrict__ bias, float* __restrict__ C,
                  int M, int N, int K,
                  long long sA, long long sB, long long sC)
{
    __shared__ float As[BK][BM + 4];
    __shared__ float Bs[BK][BN + 4];

    const int bn0 = blockIdx.x * BN;
    const int bm0 = blockIdx.y * BM;
    const float* Ab = A + (long long)blockIdx.z * sA;
    const float* Bb = Bm + (long long)blockIdx.z * sB;
    float*       Cb = C + (long long)blockIdx.z * sC;

    const int tid = threadIdx.x;
    const int tx  = tid & 15;   // 16 column groups
    const int ty  = tid >> 4;   // 16 row groups

    float acc[8][8];
#pragma unroll
    for (int i = 0; i < 8; ++i)
#pragma unroll
        for (int j = 0; j < 8; ++j) acc[i][j] = 0.f;

    for (int k0 = 0; k0 < K; k0 += BK) {
        // ---- load A tile (BMxBK), store transposed As[k][m] ----
#pragma unroll
        for (int i = 0; i < 2; ++i) {
            int f  = tid + i * 256;          // float4 index in [0,512)
            int m  = f >> 2;                 // 0..127
            int kq = (f & 3) << 2;           // 0,4,8,12
            float4 v = *reinterpret_cast<const float4*>(
                &Ab[(long long)(bm0 + m) * K + k0 + kq]);
            As[kq + 0][m] = v.x; As[kq + 1][m] = v.y;
            As[kq + 2][m] = v.z; As[kq + 3][m] = v.w;
        }
        // ---- load B tile ----
        if (B_TRANS) {
#pragma unroll
            for (int i = 0; i < 2; ++i) {
                int f  = tid + i * 256;
                int n  = f >> 2;
                int kq = (f & 3) << 2;
                float4 v = *reinterpret_cast<const float4*>(
                    &Bb[(long long)(bn0 + n) * K + k0 + kq]);
                Bs[kq + 0][n] = v.x; Bs[kq + 1][n] = v.y;
                Bs[kq + 2][n] = v.z; Bs[kq + 3][n] = v.w;
            }
        } else {
#pragma unroll
            for (int i = 0; i < 2; ++i) {
                int f = tid + i * 256;
                int k = f >> 5;              // 0..15
                int n = (f & 31) << 2;       // 0..124
                float4 v = *reinterpret_cast<const float4*>(
                    &Bb[(long long)(k0 + k) * N + bn0 + n]);
                *reinterpret_cast<float4*>(&Bs[k][n]) = v;
            }
        }
        __syncthreads();

#pragma unroll
        for (int k = 0; k < BK; ++k) {
            float ar[8], br[8];
            *reinterpret_cast<float4*>(&ar[0]) =
                *reinterpret_cast<const float4*>(&As[k][ty * 8]);
            *reinterpret_cast<float4*>(&ar[4]) =
                *reinterpret_cast<const float4*>(&As[k][ty * 8 + 4]);
            // column interleave: cols tx*4..tx*4+3 and 64+tx*4..+3 (bank-conflict free)
            *reinterpret_cast<float4*>(&br[0]) =
                *reinterpret_cast<const float4*>(&Bs[k][tx * 4]);
            *reinterpret_cast<float4*>(&br[4]) =
                *reinterpret_cast<const float4*>(&Bs[k][64 + tx * 4]);
#pragma unroll
            for (int i = 0; i < 8; ++i)
#pragma unroll
                for (int j = 0; j < 8; ++j) acc[i][j] += ar[i] * br[j];
        }
        __syncthreads();
    }

#pragma unroll
    for (int i = 0; i < 8; ++i) {
        int m = bm0 + ty * 8 + i;
#pragma unroll
        for (int half = 0; half < 2; ++half) {
            int n = bn0 + half * 64 + tx * 4;
            float4 val;
            val.x = acc[i][half * 4 + 0]; val.y = acc[i][half * 4 + 1];
            val.z = acc[i][half * 4 + 2]; val.w = acc[i][half * 4 + 3];
            if (BIAS) {
                float4 bv4 = *reinterpret_cast<const float4*>(&bias[n]);
                val.x += bv4.x; val.y += bv4.y; val.z += bv4.z; val.w += bv4.w;
            }
            float* cp = &Cb[(long long)m * N + n];
            if (ACCUM) {
                float4 old = *reinterpret_cast<const float4*>(cp);
                val.x += old.x; val.y += old.y; val.z += old.z; val.w += old.w;
            }
            *reinterpret_cast<float4*>(cp) = val;
        }
    }
}

// ---------------------------------------------------------------------------
// attn2 + scale + mask:  scores[b,s,t] = (scores[b,s,t] + q[b,s,:]·k_bias[s,t,:]) * scale
// Block = (s, t-tile of 256). k_bias read exactly once (all 16 batches share it).
// ---------------------------------------------------------------------------
__global__ __launch_bounds__(256)
void attn2_kernel(const float* __restrict__ q, const float* __restrict__ kb,
                  const int* __restrict__ mask, float* __restrict__ scores)
{
    const int s = blockIdx.x;
    const int t = blockIdx.y * 256 + threadIdx.x;
    __shared__ float qs[16][128];   // q[:, s, :]
#pragma unroll
    for (int i = 0; i < 2; ++i) {
        int f  = threadIdx.x + i * 256;   // float4 idx in [0,512)
        int b  = f >> 5;
        int d4 = (f & 31) << 2;
        *reinterpret_cast<float4*>(&qs[b][d4]) =
            *reinterpret_cast<const float4*>(&q[((long long)b * Sq + s) * Dd + d4]);
    }
    __syncthreads();

    float acc[16];
#pragma unroll
    for (int b = 0; b < 16; ++b) acc[b] = 0.f;

    const float4* kb4 = reinterpret_cast<const float4*>(&kb[((long long)s * Sq + t) * Dd]);
#pragma unroll 8
    for (int dv = 0; dv < 32; ++dv) {
        float4 kv = kb4[dv];
        int d = dv << 2;
#pragma unroll
        for (int b = 0; b < 16; ++b) {
            float4 qv = *reinterpret_cast<const float4*>(&qs[b][d]);
            acc[b] += qv.x * kv.x + qv.y * kv.y + qv.z * kv.z + qv.w * kv.w;
        }
    }

    const float scale = 0.08838834764831845f;  // 1/sqrt(128)
#pragma unroll
    for (int b = 0; b < 16; ++b) {
        long long idx = ((long long)b * Sq + s) * (long long)Sq + t;
        float sc = (scores[idx] + acc[b]) * scale;
        if (mask[b * Sq + t] == 0) sc = -1e9f;
        scores[idx] = sc;
    }
}

// ---------------------------------------------------------------------------
// Row softmax over t (row length 1024), block per row, 256 threads x float4.
// ---------------------------------------------------------------------------
__global__ __launch_bounds__(256)
void softmax_kernel(float* __restrict__ scores)
{
    long long row = blockIdx.x;
    float* p = scores + row * Sq;
    int tid = threadIdx.x;
    float4 x = *reinterpret_cast<const float4*>(&p[tid << 2]);

    float m = fmaxf(fmaxf(x.x, x.y), fmaxf(x.z, x.w));
    __shared__ float red[8];
#pragma unroll
    for (int o = 16; o > 0; o >>= 1) m = fmaxf(m, __shfl_xor_sync(0xffffffffu, m, o));
    if ((tid & 31) == 0) red[tid >> 5] = m;
    __syncthreads();
    float M = red[0];
#pragma unroll
    for (int i = 1; i < 8; ++i) M = fmaxf(M, red[i]);

    float e0 = __expf(x.x - M), e1 = __expf(x.y - M);
    float e2 = __expf(x.z - M), e3 = __expf(x.w - M);
    float ssum = e0 + e1 + e2 + e3;
#pragma unroll
    for (int o = 16; o > 0; o >>= 1) ssum += __shfl_xor_sync(0xffffffffu, ssum, o);
    __syncthreads();
    if ((tid & 31) == 0) red[tid >> 5] = ssum;
    __syncthreads();
    float Ssum = 0.f;
#pragma unroll
    for (int i = 0; i < 8; ++i) Ssum += red[i];
    float inv = 1.0f / Ssum;

    float4 o4 = {e0 * inv, e1 * inv, e2 * inv, e3 * inv};
    *reinterpret_cast<float4*>(&p[tid << 2]) = o4;
}

// ---------------------------------------------------------------------------
// values2: out[b,s,d] = sum_t w[b,s,t] * v_bias[s,t,d]  (writes out, beta=0)
// Block per s; v_bias read exactly once. thread -> (b = tid/16, d-cols tid%16*4 and +64)
// ---------------------------------------------------------------------------
__global__ __launch_bounds__(256)
void values2_kernel(const float* __restrict__ w, const float* __restrict__ vb,
                    float* __restrict__ out)
{
    const int s = blockIdx.x;
    __shared__ float vbs[32][128];
    __shared__ float ws[16][33];
    const int tid = threadIdx.x;
    const int b = tid >> 4;            // 0..15
    const int c = (tid & 15) << 2;     // 0,4,...,60

    float acc[8] = {0, 0, 0, 0, 0, 0, 0, 0};
    for (int t0 = 0; t0 < Sq; t0 += 32) {
#pragma unroll
        for (int i = 0; i < 4; ++i) {
            int f  = tid + i * 256;        // float4 idx in [0,1024)
            int tt = f >> 5;
            int dd = (f & 31) << 2;
            *reinterpret_cast<float4*>(&vbs[tt][dd]) =
                *reinterpret_cast<const float4*>(&vb[((long long)s * Sq + t0 + tt) * Dd + dd]);
        }
#pragma unroll
        for (int i = 0; i < 2; ++i) {
            int g = tid + i * 256;
            int bb = g >> 5, tt = g & 31;
            ws[bb][tt] = w[((long long)bb * Sq + s) * (long long)Sq + t0 + tt];
        }
        __syncthreads();
#pragma unroll
        for (int tt = 0; tt < 32; ++tt) {
            float wv = ws[b][tt];
            float4 v0 = *reinterpret_cast<const float4*>(&vbs[tt][c]);
            float4 v1 = *reinterpret_cast<const float4*>(&vbs[tt][c + 64]);
            acc[0] += wv * v0.x; acc[1] += wv * v0.y;
            acc[2] += wv * v0.z; acc[3] += wv * v0.w;
            acc[4] += wv * v1.x; acc[5] += wv * v1.y;
            acc[6] += wv * v1.z; acc[7] += wv * v1.w;
        }
        __syncthreads();
    }
    float4 o0 = {acc[0], acc[1], acc[2], acc[3]};
    float4 o1 = {acc[4], acc[5], acc[6], acc[7]};
    float* op = &out[((long long)b * Sq + s) * Dd];
    *reinterpret_cast<float4*>(&op[c])      = o0;
    *reinterpret_cast<float4*>(&op[c + 64]) = o1;
}

// ---------------------------------------------------------------------------
extern "C" void kernel_launch(void* const* d_in, const int* in_sizes, int n_in,
                              void* d_out, int out_size)
{
    const float* query  = (const float*)d_in[0];
    const float* key_   = (const float*)d_in[1];
    const float* value  = (const float*)d_in[2];
    const int*   mask   = (const int*)  d_in[3];
    const float* Wq     = (const float*)d_in[4];
    const float* bq     = (const float*)d_in[5];
    const float* Wk     = (const float*)d_in[6];
    const float* bk     = (const float*)d_in[7];
    const float* Wv     = (const float*)d_in[8];
    const float* bv     = (const float*)d_in[9];
    const float* k_bias = (const float*)d_in[10];
    const float* v_bias = (const float*)d_in[11];
    float* out = (float*)d_out;

    void *pq, *pk, *pv, *ps;
    cudaGetSymbolAddress(&pq, g_q);
    cudaGetSymbolAddress(&pk, g_k);
    cudaGetSymbolAddress(&pv, g_v);
    cudaGetSymbolAddress(&ps, g_scores);
    float* q  = (float*)pq;
    float* k  = (float*)pk;
    float* v  = (float*)pv;
    float* sc = (float*)ps;

    dim3 blk(256);

    // Projections: [16384,1024] x [128,1024]^T + bias
    dim3 gproj(1, (Bsz * Sq) / BM, 1);
    sgemm_kernel<true, false, true><<<gproj, blk>>>(query, Wq, bq, q, Bsz * Sq, Dd, Hd, 0, 0, 0);
    sgemm_kernel<true, false, true><<<gproj, blk>>>(key_,  Wk, bk, k, Bsz * Sq, Dd, Hd, 0, 0, 0);
    sgemm_kernel<true, false, true><<<gproj, blk>>>(value, Wv, bv, v, Bsz * Sq, Dd, Hd, 0, 0, 0);

    // attn1: scores[b] = q[b] (1024x128) * k[b]^T  (write)
    dim3 g2(Sq / BN, Sq / BM, Bsz);
    sgemm_kernel<true, false, false><<<g2, blk>>>(q, k, nullptr, sc, Sq, Sq, Dd,
        (long long)Sq * Dd, (long long)Sq * Dd, (long long)Sq * Sq);

    // attn2 + scale + mask  (k_bias read once)
    attn2_kernel<<<dim3(Sq, Sq / 256), blk>>>(q, k_bias, mask, sc);

    // softmax over t
    softmax_kernel<<<Bsz * Sq, blk>>>(sc);

    // values2: out = w @ v_bias (per s)   (v_bias read once)
    values2_kernel<<<Sq, blk>>>(sc, v_bias, out);

    // values1: out += w[b] (1024x1024) * v[b] (1024x128)
    dim3 g6(Dd / BN, Sq / BM, Bsz);
    sgemm_kernel<false, true, false><<<g6, blk>>>(sc, v, nullptr, out, Sq, Dd, Sq,
        (long long)Sq * Sq, (long long)Sq * Dd, (long long)Sq * Dd);
}

// round 5
// speedup vs baseline: 1.2516x; 1.2462x over previous
#include <cuda_runtime.h>
#include <cuda_bf16.h>
#include <cstdint>

constexpr int Bsz = 16;
constexpr int Sq  = 1024;
constexpr int Hd  = 1024;
constexpr int Dd  = 128;

__device__ float g_q[Bsz * Sq * Dd];
__device__ float g_k[Bsz * Sq * Dd];
__device__ float g_vT[Dd * Bsz * Sq];                // v transposed: [d][b*1024+t]
__device__ float g_scores[(size_t)Bsz * Sq * Sq];

// ======================= helpers =======================
__device__ __forceinline__ uint32_t smem_u32(const void* p) {
    uint32_t a;
    asm("{ .reg .u64 t; cvta.to.shared.u64 t, %1; cvt.u32.u64 %0, t; }" : "=r"(a) : "l"(p));
    return a;
}
__device__ __forceinline__ void ldsm4(uint32_t addr, uint32_t* r) {
    asm volatile("ldmatrix.sync.aligned.m8n8.x4.shared.b16 {%0,%1,%2,%3}, [%4];"
                 : "=r"(r[0]), "=r"(r[1]), "=r"(r[2]), "=r"(r[3]) : "r"(addr));
}
__device__ __forceinline__ void mma16816(float* c, const uint32_t* a, uint32_t b0, uint32_t b1) {
    asm volatile(
        "mma.sync.aligned.m16n8k16.row.col.f32.bf16.bf16.f32 "
        "{%0,%1,%2,%3}, {%4,%5,%6,%7}, {%8,%9}, {%0,%1,%2,%3};"
        : "+f"(c[0]), "+f"(c[1]), "+f"(c[2]), "+f"(c[3])
        : "r"(a[0]), "r"(a[1]), "r"(a[2]), "r"(a[3]), "r"(b0), "r"(b1));
}
// fp32 float4 -> bf16 hi pair / lo pair (bf16x3 decomposition)
__device__ __forceinline__ void bf16x3_split(float4 v, uint32_t& h01, uint32_t& h23,
                                             uint32_t& l01, uint32_t& l23) {
    asm("cvt.rn.bf16x2.f32 %0, %1, %2;" : "=r"(h01) : "f"(v.y), "f"(v.x));
    asm("cvt.rn.bf16x2.f32 %0, %1, %2;" : "=r"(h23) : "f"(v.w), "f"(v.z));
    float h0 = __uint_as_float(h01 << 16);
    float h1 = __uint_as_float(h01 & 0xffff0000u);
    float h2 = __uint_as_float(h23 << 16);
    float h3 = __uint_as_float(h23 & 0xffff0000u);
    float l0 = v.x - h0, l1 = v.y - h1, l2 = v.z - h2, l3 = v.w - h3;
    asm("cvt.rn.bf16x2.f32 %0, %1, %2;" : "=r"(l01) : "f"(l1), "f"(l0));
    asm("cvt.rn.bf16x2.f32 %0, %1, %2;" : "=r"(l23) : "f"(l3), "f"(l2));
}

// ======================= bf16x3 tensor-core GEMM =======================
// C[128x128] per CTA.  A:[M,K] lda (K-contig).  B:[N,K] ldb (K-contig).  D=A@B^T.
// CT_OUT: write D[m][n] -> C[n*ldc + m_global] (transposed output).
constexpr int KPAD = 72;                      // bf16 elems per smem row (144B, conflict-free)
constexpr int PLB  = 128 * KPAD * 2;          // plane bytes = 18432
constexpr int SMEM_GEMM = 4 * PLB;            // Ah, Al, Bh, Bl = 73728 B

template<bool BIAS, bool ACCUM, bool CT_OUT>
__global__ void __launch_bounds__(256, 1)
mma_gemm_kernel(const float* __restrict__ A, const float* __restrict__ B,
                const float* __restrict__ bias, float* __restrict__ C,
                int K, int lda, int ldb, int ldc,
                long long sA, long long sB, long long sC)
{
    extern __shared__ char sm[];
    const uint32_t sb = smem_u32(sm);
    const int tid  = threadIdx.x;
    const int lane = tid & 31, wid = tid >> 5;
    const int wm = wid >> 2, wn = wid & 3;          // warp tile 64m x 32n
    const int bn0 = blockIdx.x * 128;
    const int bm0 = blockIdx.y * 128;
    const float* Ab = A + blockIdx.z * sA + (long long)bm0 * lda;
    const float* Bb = B + blockIdx.z * sB + (long long)bn0 * ldb;
    float* Cb = C + blockIdx.z * sC;

    float acc[4][4][4];
#pragma unroll
    for (int i = 0; i < 4; ++i)
#pragma unroll
        for (int j = 0; j < 4; ++j)
#pragma unroll
            for (int r = 0; r < 4; ++r) acc[i][j][r] = 0.f;

    const int r0 = tid >> 4;          // base row 0..15 (+16*i)
    const int c4 = tid & 15;          // float4 col within K64 chunk
    const int nch = K >> 6;

    float4 ra[8], rb[8];
    // prologue: load chunk 0
#pragma unroll
    for (int i = 0; i < 8; ++i) {
        const int r = r0 + i * 16;
        ra[i] = *(const float4*)(Ab + (long long)r * lda + (c4 << 2));
        rb[i] = *(const float4*)(Bb + (long long)r * ldb + (c4 << 2));
    }
    // store chunk 0 (convert)
    {
        char* pAh = sm;             char* pAl = sm + PLB;
        char* pBh = sm + 2 * PLB;   char* pBl = sm + 3 * PLB;
#pragma unroll
        for (int i = 0; i < 8; ++i) {
            const int r = r0 + i * 16;
            const uint32_t off = (uint32_t)(r * KPAD + (c4 << 2)) * 2;
            uint32_t h01, h23, l01, l23;
            bf16x3_split(ra[i], h01, h23, l01, l23);
            *(uint2*)(pAh + off) = make_uint2(h01, h23);
            *(uint2*)(pAl + off) = make_uint2(l01, l23);
            bf16x3_split(rb[i], h01, h23, l01, l23);
            *(uint2*)(pBh + off) = make_uint2(h01, h23);
            *(uint2*)(pBl + off) = make_uint2(l01, l23);
        }
    }
    __syncthreads();

    const int lrow = lane & 15;
    const int lk   = (lane >> 4) << 3;

    for (int c = 0; c < nch; ++c) {
        const bool more = (c + 1) < nch;
        if (more) {
            const float* Ac = Ab + (c + 1) * 64;
            const float* Bc = Bb + (c + 1) * 64;
#pragma unroll
            for (int i = 0; i < 8; ++i) {
                const int r = r0 + i * 16;
                ra[i] = *(const float4*)(Ac + (long long)r * lda + (c4 << 2));
                rb[i] = *(const float4*)(Bc + (long long)r * ldb + (c4 << 2));
            }
        }
        // MMA over the chunk in smem: 4 k16 steps x 3 planes
#pragma unroll
        for (int ks = 0; ks < 4; ++ks) {
            const int k0 = ks * 16;
            uint32_t Ah[4][4], Al[4][4], Bh[2][4], Bl[2][4];
#pragma unroll
            for (int i = 0; i < 4; ++i) {
                const uint32_t rowoff =
                    (uint32_t)((wm * 64 + i * 16 + lrow) * KPAD + k0 + lk) * 2;
                ldsm4(sb + rowoff, Ah[i]);
                ldsm4(sb + PLB + rowoff, Al[i]);
            }
#pragma unroll
            for (int jj = 0; jj < 2; ++jj) {
                const uint32_t rowoff =
                    (uint32_t)((wn * 32 + jj * 16 + lrow) * KPAD + k0 + lk) * 2;
                ldsm4(sb + 2 * PLB + rowoff, Bh[jj]);
                ldsm4(sb + 3 * PLB + rowoff, Bl[jj]);
            }
#pragma unroll
            for (int i = 0; i < 4; ++i)
#pragma unroll
                for (int j = 0; j < 4; ++j) {
                    const int jj = j >> 1, ss = j & 1;
                    // n-tile j frag: {r[ss], r[ss+2]} of the jj-th x4 load
                    mma16816(acc[i][j], Ah[i], Bh[jj][ss], Bh[jj][ss + 2]);
                    mma16816(acc[i][j], Ah[i], Bl[jj][ss], Bl[jj][ss + 2]);
                    mma16816(acc[i][j], Al[i], Bh[jj][ss], Bh[jj][ss + 2]);
                }
        }
        __syncthreads();
        if (more) {
            char* pAh = sm;             char* pAl = sm + PLB;
            char* pBh = sm + 2 * PLB;   char* pBl = sm + 3 * PLB;
#pragma unroll
            for (int i = 0; i < 8; ++i) {
                const int r = r0 + i * 16;
                const uint32_t off = (uint32_t)(r * KPAD + (c4 << 2)) * 2;
                uint32_t h01, h23, l01, l23;
                bf16x3_split(ra[i], h01, h23, l01, l23);
                *(uint2*)(pAh + off) = make_uint2(h01, h23);
                *(uint2*)(pAl + off) = make_uint2(l01, l23);
                bf16x3_split(rb[i], h01, h23, l01, l23);
                *(uint2*)(pBh + off) = make_uint2(h01, h23);
                *(uint2*)(pBl + off) = make_uint2(l01, l23);
            }
            __syncthreads();
        }
    }

    // epilogue
    const int g  = lane >> 2;
    const int tq = lane & 3;
#pragma unroll
    for (int i = 0; i < 4; ++i)
#pragma unroll
        for (int j = 0; j < 4; ++j) {
            const int row = bm0 + wm * 64 + i * 16 + g;
            const int col = bn0 + wn * 32 + j * 8 + tq * 2;
#pragma unroll
            for (int h = 0; h < 2; ++h) {   // h=0: row, h=1: row+8
                const int rr = row + h * 8;
                float v0 = acc[i][j][h * 2 + 0];
                float v1 = acc[i][j][h * 2 + 1];
                if (BIAS) { v0 += bias[col]; v1 += bias[col + 1]; }
                if (CT_OUT) {
                    Cb[(long long)col * ldc + rr]       = v0;
                    Cb[(long long)(col + 1) * ldc + rr] = v1;
                } else {
                    float* cp = Cb + (long long)rr * ldc + col;
                    if (ACCUM) { v0 += cp[0]; v1 += cp[1]; }
                    cp[0] = v0; cp[1] = v1;
                }
            }
        }
}

// ======================= fused attn2 + scale + mask + softmax =======================
// Block per s.  w[b][t] = sum_d q[b,s,d]*k_bias[s,t,d]; then per-b row softmax of
// (scores_attn1 + w)*scale with mask.  k_bias read exactly once.
constexpr int SMEM_ATTN2 = (16 * 1024 + 16 * 132 + 32 * 132) * 4;   // 90880 B

__global__ void __launch_bounds__(256, 1)
attn2sm_kernel(const float* __restrict__ q, const float* __restrict__ kb,
               const int* __restrict__ mask, float* __restrict__ scores)
{
    extern __shared__ float smf[];
    float* w_s  = smf;                   // [16][1024]
    float* q_s  = smf + 16 * 1024;       // [16][132]
    float* kb_s = q_s + 16 * 132;        // [32][132]
    const int s = blockIdx.x;
    const int tid = threadIdx.x;

#pragma unroll
    for (int i = 0; i < 2; ++i) {
        int f = tid + i * 256;
        int b = f >> 5, d4 = (f & 31) << 2;
        *(float4*)&q_s[b * 132 + d4] =
            *(const float4*)&q[((long long)b * Sq + s) * Dd + d4];
    }

    const int b  = tid >> 4;
    const int t8 = tid & 15;
    for (int t0 = 0; t0 < Sq; t0 += 32) {
#pragma unroll
        for (int i = 0; i < 4; ++i) {
            int f = tid + i * 256;
            int tt = f >> 5, dd = (f & 31) << 2;
            *(float4*)&kb_s[tt * 132 + dd] =
                *(const float4*)&kb[((long long)s * Sq + t0 + tt) * Dd + dd];
        }
        __syncthreads();
        float a0 = 0.f, a1 = 0.f;
#pragma unroll 8
        for (int d4 = 0; d4 < 32; ++d4) {
            float4 qv = *(const float4*)&q_s[b * 132 + (d4 << 2)];
            float4 k0 = *(const float4*)&kb_s[t8 * 132 + (d4 << 2)];
            float4 k1 = *(const float4*)&kb_s[(t8 + 16) * 132 + (d4 << 2)];
            a0 += qv.x * k0.x + qv.y * k0.y + qv.z * k0.z + qv.w * k0.w;
            a1 += qv.x * k1.x + qv.y * k1.y + qv.z * k1.z + qv.w * k1.w;
        }
        w_s[b * 1024 + t0 + t8]      = a0;
        w_s[b * 1024 + t0 + t8 + 16] = a1;
        __syncthreads();
    }

    // softmax: warp w handles rows b = 2w, 2w+1
    const int lane = tid & 31, wd = tid >> 5;
    const float scale = 0.08838834764831845f;
#pragma unroll 1
    for (int r = 0; r < 2; ++r) {
        const int bb = wd * 2 + r;
        float* wrow = &w_s[bb * 1024];
        const long long gbase = ((long long)bb * Sq + s) * (long long)Sq;
        float4 vals[8];
        float mx = -3.0e38f;
#pragma unroll
        for (int j = 0; j < 8; ++j) {
            const int t4 = lane + j * 32;       // float4 index
            float4 gsc = *(const float4*)&scores[gbase + t4 * 4];
            float4 ww  = *(const float4*)&wrow[t4 * 4];
            int4   mk  = *(const int4*)&mask[bb * Sq + t4 * 4];
            float4 v;
            v.x = (gsc.x + ww.x) * scale; if (mk.x == 0) v.x = -1e9f;
            v.y = (gsc.y + ww.y) * scale; if (mk.y == 0) v.y = -1e9f;
            v.z = (gsc.z + ww.z) * scale; if (mk.z == 0) v.z = -1e9f;
            v.w = (gsc.w + ww.w) * scale; if (mk.w == 0) v.w = -1e9f;
            vals[j] = v;
            mx = fmaxf(mx, fmaxf(fmaxf(v.x, v.y), fmaxf(v.z, v.w)));
        }
#pragma unroll
        for (int o = 16; o > 0; o >>= 1) mx = fmaxf(mx, __shfl_xor_sync(0xffffffffu, mx, o));
        float sum = 0.f;
#pragma unroll
        for (int j = 0; j < 8; ++j) {
            float4 v = vals[j];
            v.x = __expf(v.x - mx); v.y = __expf(v.y - mx);
            v.z = __expf(v.z - mx); v.w = __expf(v.w - mx);
            vals[j] = v;
            sum += v.x + v.y + v.z + v.w;
        }
#pragma unroll
        for (int o = 16; o > 0; o >>= 1) sum += __shfl_xor_sync(0xffffffffu, sum, o);
        const float inv = 1.0f / sum;
#pragma unroll
        for (int j = 0; j < 8; ++j) {
            const int t4 = lane + j * 32;
            float4 v = vals[j];
            v.x *= inv; v.y *= inv; v.z *= inv; v.w *= inv;
            *(float4*)&scores[gbase + t4 * 4] = v;
        }
    }
}

// ======================= values2 =======================
__global__ __launch_bounds__(256)
void values2_kernel(const float* __restrict__ w, const float* __restrict__ vb,
                    float* __restrict__ out)
{
    const int s = blockIdx.x;
    __shared__ float vbs[32][128];
    __shared__ float ws[16][33];
    const int tid = threadIdx.x;
    const int b = tid >> 4;
    const int c = (tid & 15) << 2;

    float acc[8] = {0, 0, 0, 0, 0, 0, 0, 0};
    for (int t0 = 0; t0 < Sq; t0 += 32) {
#pragma unroll
        for (int i = 0; i < 4; ++i) {
            int f  = tid + i * 256;
            int tt = f >> 5;
            int dd = (f & 31) << 2;
            *(float4*)&vbs[tt][dd] =
                *(const float4*)&vb[((long long)s * Sq + t0 + tt) * Dd + dd];
        }
#pragma unroll
        for (int i = 0; i < 2; ++i) {
            int g = tid + i * 256;
            int bb = g >> 5, tt = g & 31;
            ws[bb][tt] = w[((long long)bb * Sq + s) * (long long)Sq + t0 + tt];
        }
        __syncthreads();
#pragma unroll
        for (int tt = 0; tt < 32; ++tt) {
            float wv = ws[b][tt];
            float4 v0 = *(const float4*)&vbs[tt][c];
            float4 v1 = *(const float4*)&vbs[tt][c + 64];
            acc[0] += wv * v0.x; acc[1] += wv * v0.y;
            acc[2] += wv * v0.z; acc[3] += wv * v0.w;
            acc[4] += wv * v1.x; acc[5] += wv * v1.y;
            acc[6] += wv * v1.z; acc[7] += wv * v1.w;
        }
        __syncthreads();
    }
    float4 o0 = {acc[0], acc[1], acc[2], acc[3]};
    float4 o1 = {acc[4], acc[5], acc[6], acc[7]};
    float* op = &out[((long long)b * Sq + s) * Dd];
    *(float4*)&op[c]      = o0;
    *(float4*)&op[c + 64] = o1;
}

// ======================= launch =======================
extern "C" void kernel_launch(void* const* d_in, const int* in_sizes, int n_in,
                              void* d_out, int out_size)
{
    const float* query  = (const float*)d_in[0];
    const float* key_   = (const float*)d_in[1];
    const float* value  = (const float*)d_in[2];
    const int*   mask   = (const int*)  d_in[3];
    const float* Wq     = (const float*)d_in[4];
    const float* bq     = (const float*)d_in[5];
    const float* Wk     = (const float*)d_in[6];
    const float* bk     = (const float*)d_in[7];
    const float* Wv     = (const float*)d_in[8];
    const float* bv     = (const float*)d_in[9];
    const float* k_bias = (const float*)d_in[10];
    const float* v_bias = (const float*)d_in[11];
    float* out = (float*)d_out;

    void *pq, *pk, *pv, *ps;
    cudaGetSymbolAddress(&pq, g_q);
    cudaGetSymbolAddress(&pk, g_k);
    cudaGetSymbolAddress(&pv, g_vT);
    cudaGetSymbolAddress(&ps, g_scores);
    float* q  = (float*)pq;
    float* k  = (float*)pk;
    float* vT = (float*)pv;
    float* sc = (float*)ps;

    cudaFuncSetAttribute(mma_gemm_kernel<true,  false, false>,
                         cudaFuncAttributeMaxDynamicSharedMemorySize, SMEM_GEMM);
    cudaFuncSetAttribute(mma_gemm_kernel<true,  false, true>,
                         cudaFuncAttributeMaxDynamicSharedMemorySize, SMEM_GEMM);
    cudaFuncSetAttribute(mma_gemm_kernel<false, false, false>,
                         cudaFuncAttributeMaxDynamicSharedMemorySize, SMEM_GEMM);
    cudaFuncSetAttribute(mma_gemm_kernel<false, true,  false>,
                         cudaFuncAttributeMaxDynamicSharedMemorySize, SMEM_GEMM);
    cudaFuncSetAttribute(attn2sm_kernel,
                         cudaFuncAttributeMaxDynamicSharedMemorySize, SMEM_ATTN2);

    dim3 blk(256);

    // Projections: [16384,1024] x W^T + bias   (M=16384, N=128, K=1024)
    dim3 gp(1, (Bsz * Sq) / 128, 1);
    mma_gemm_kernel<true, false, false><<<gp, blk, SMEM_GEMM>>>(
        query, Wq, bq, q, Hd, Hd, Hd, Dd, 0, 0, 0);
    mma_gemm_kernel<true, false, false><<<gp, blk, SMEM_GEMM>>>(
        key_,  Wk, bk, k, Hd, Hd, Hd, Dd, 0, 0, 0);
    mma_gemm_kernel<true, false, true><<<gp, blk, SMEM_GEMM>>>(
        value, Wv, bv, vT, Hd, Hd, Hd, Bsz * Sq, 0, 0, 0);

    // attn1: scores[b] = q[b] @ k[b]^T   (M=N=1024, K=128)
    dim3 g1(Sq / 128, Sq / 128, Bsz);
    mma_gemm_kernel<false, false, false><<<g1, blk, SMEM_GEMM>>>(
        q, k, nullptr, sc, Dd, Dd, Dd, Sq,
        (long long)Sq * Dd, (long long)Sq * Dd, (long long)Sq * Sq);

    // fused attn2 + scale + mask + softmax (k_bias read once)
    attn2sm_kernel<<<Sq, blk, SMEM_ATTN2>>>(q, k_bias, mask, sc);

    // values2: out = w @ v_bias (per s, v_bias read once)
    values2_kernel<<<Sq, blk>>>(sc, v_bias, out);

    // values1: out += w[b] @ v[b]   (A=w K-contig over t, B=vT[d][bS+t])
    dim3 g6(Dd / 128, Sq / 128, Bsz);
    mma_gemm_kernel<false, true, false><<<g6, blk, SMEM_GEMM>>>(
        sc, vT, nullptr, out, Sq, Sq, Bsz * Sq, Dd,
        (long long)Sq * Sq, (long long)Sq, (long long)Sq * Dd);
}

// round 6
// speedup vs baseline: 2.4573x; 1.9633x over previous
#include <cuda_runtime.h>
#include <cuda_bf16.h>
#include <cstdint>

constexpr int Bsz = 16;
constexpr int Sq  = 1024;
constexpr int Hd  = 1024;
constexpr int Dd  = 128;

__device__ float g_q[Bsz * Sq * Dd];
__device__ float g_k[Bsz * Sq * Dd];
__device__ float g_vT[Dd * Bsz * Sq];
__device__ float g_scores[(size_t)Bsz * Sq * Sq];

// ======================= helpers =======================
__device__ __forceinline__ uint32_t smem_u32(const void* p) {
    uint32_t a;
    asm("{ .reg .u64 t; cvta.to.shared.u64 t, %1; cvt.u32.u64 %0, t; }" : "=r"(a) : "l"(p));
    return a;
}
__device__ __forceinline__ void ldsm4(uint32_t addr, uint32_t* r) {
    asm volatile("ldmatrix.sync.aligned.m8n8.x4.shared.b16 {%0,%1,%2,%3}, [%4];"
                 : "=r"(r[0]), "=r"(r[1]), "=r"(r[2]), "=r"(r[3]) : "r"(addr));
}
__device__ __forceinline__ void ldsm4t(uint32_t addr, uint32_t* r) {
    asm volatile("ldmatrix.sync.aligned.m8n8.x4.trans.shared.b16 {%0,%1,%2,%3}, [%4];"
                 : "=r"(r[0]), "=r"(r[1]), "=r"(r[2]), "=r"(r[3]) : "r"(addr));
}
__device__ __forceinline__ void mma16816(float* c, const uint32_t* a, uint32_t b0, uint32_t b1) {
    asm volatile(
        "mma.sync.aligned.m16n8k16.row.col.f32.bf16.bf16.f32 "
        "{%0,%1,%2,%3}, {%4,%5,%6,%7}, {%8,%9}, {%0,%1,%2,%3};"
        : "+f"(c[0]), "+f"(c[1]), "+f"(c[2]), "+f"(c[3])
        : "r"(a[0]), "r"(a[1]), "r"(a[2]), "r"(a[3]), "r"(b0), "r"(b1));
}
__device__ __forceinline__ void bf16x3_split(float4 v, uint32_t& h01, uint32_t& h23,
                                             uint32_t& l01, uint32_t& l23) {
    asm("cvt.rn.bf16x2.f32 %0, %1, %2;" : "=r"(h01) : "f"(v.y), "f"(v.x));
    asm("cvt.rn.bf16x2.f32 %0, %1, %2;" : "=r"(h23) : "f"(v.w), "f"(v.z));
    float h0 = __uint_as_float(h01 << 16);
    float h1 = __uint_as_float(h01 & 0xffff0000u);
    float h2 = __uint_as_float(h23 << 16);
    float h3 = __uint_as_float(h23 & 0xffff0000u);
    float l0 = v.x - h0, l1 = v.y - h1, l2 = v.z - h2, l3 = v.w - h3;
    asm("cvt.rn.bf16x2.f32 %0, %1, %2;" : "=r"(l01) : "f"(l1), "f"(l0));
    asm("cvt.rn.bf16x2.f32 %0, %1, %2;" : "=r"(l23) : "f"(l3), "f"(l2));
}
__device__ __forceinline__ void split2(float2 v, uint32_t& h, uint32_t& l) {
    asm("cvt.rn.bf16x2.f32 %0, %1, %2;" : "=r"(h) : "f"(v.y), "f"(v.x));
    float h0 = __uint_as_float(h << 16);
    float h1 = __uint_as_float(h & 0xffff0000u);
    float l0 = v.x - h0, l1 = v.y - h1;
    asm("cvt.rn.bf16x2.f32 %0, %1, %2;" : "=r"(l) : "f"(l1), "f"(l0));
}

// ======================= bf16x3 tensor-core GEMM (double-buffered) =======================
constexpr int KPAD = 72;
constexpr int PLB  = 128 * KPAD * 2;          // 18432 B per plane
constexpr int SMEM_GEMM = 8 * PLB;            // 2 buffers x 4 planes = 147456 B

template<bool BIAS, bool ACCUM, bool CT_OUT>
__global__ void __launch_bounds__(256, 1)
mma_gemm_kernel(const float* __restrict__ A, const float* __restrict__ B,
                const float* __restrict__ bias, float* __restrict__ C,
                int K, int lda, int ldb, int ldc,
                long long sA, long long sB, long long sC)
{
    extern __shared__ char sm[];
    const uint32_t sb = smem_u32(sm);
    const int tid  = threadIdx.x;
    const int lane = tid & 31, wid = tid >> 5;
    const int wm = wid >> 2, wn = wid & 3;
    const int bn0 = blockIdx.x * 128;
    const int bm0 = blockIdx.y * 128;
    const float* Ab = A + blockIdx.z * sA + (long long)bm0 * lda;
    const float* Bb = B + blockIdx.z * sB + (long long)bn0 * ldb;
    float* Cb = C + blockIdx.z * sC;

    float acc[4][4][4];
#pragma unroll
    for (int i = 0; i < 4; ++i)
#pragma unroll
        for (int j = 0; j < 4; ++j)
#pragma unroll
            for (int r = 0; r < 4; ++r) acc[i][j][r] = 0.f;

    const int r0 = tid >> 4;
    const int c4 = tid & 15;
    const int nch = K >> 6;

    float4 ra[8], rb[8];
#pragma unroll
    for (int i = 0; i < 8; ++i) {
        const int r = r0 + i * 16;
        ra[i] = *(const float4*)(Ab + (long long)r * lda + (c4 << 2));
        rb[i] = *(const float4*)(Bb + (long long)r * ldb + (c4 << 2));
    }
    {   // store chunk0 -> buffer 0
        char* base = sm;
#pragma unroll
        for (int i = 0; i < 8; ++i) {
            const int r = r0 + i * 16;
            const uint32_t off = (uint32_t)(r * KPAD + (c4 << 2)) * 2;
            uint32_t h01, h23, l01, l23;
            bf16x3_split(ra[i], h01, h23, l01, l23);
            *(uint2*)(base + off)       = make_uint2(h01, h23);
            *(uint2*)(base + PLB + off) = make_uint2(l01, l23);
            bf16x3_split(rb[i], h01, h23, l01, l23);
            *(uint2*)(base + 2 * PLB + off) = make_uint2(h01, h23);
            *(uint2*)(base + 3 * PLB + off) = make_uint2(l01, l23);
        }
    }
    __syncthreads();

    const int lrow = lane & 15;
    const int lk   = (lane >> 4) << 3;

    for (int c = 0; c < nch; ++c) {
        const bool more = (c + 1) < nch;
        if (more) {
            const float* Ac = Ab + (c + 1) * 64;
            const float* Bc = Bb + (c + 1) * 64;
#pragma unroll
            for (int i = 0; i < 8; ++i) {
                const int r = r0 + i * 16;
                ra[i] = *(const float4*)(Ac + (long long)r * lda + (c4 << 2));
                rb[i] = *(const float4*)(Bc + (long long)r * ldb + (c4 << 2));
            }
        }
        const uint32_t bo = (uint32_t)(c & 1) * 4u * PLB;
#pragma unroll
        for (int ks = 0; ks < 4; ++ks) {
            const int k0 = ks * 16;
            uint32_t Ah[4][4], Al[4][4], Bh[2][4], Bl[2][4];
#pragma unroll
            for (int i = 0; i < 4; ++i) {
                const uint32_t rowoff =
                    (uint32_t)((wm * 64 + i * 16 + lrow) * KPAD + k0 + lk) * 2;
                ldsm4(sb + bo + rowoff, Ah[i]);
                ldsm4(sb + bo + PLB + rowoff, Al[i]);
            }
#pragma unroll
            for (int jj = 0; jj < 2; ++jj) {
                const uint32_t rowoff =
                    (uint32_t)((wn * 32 + jj * 16 + lrow) * KPAD + k0 + lk) * 2;
                ldsm4(sb + bo + 2 * PLB + rowoff, Bh[jj]);
                ldsm4(sb + bo + 3 * PLB + rowoff, Bl[jj]);
            }
#pragma unroll
            for (int i = 0; i < 4; ++i)
#pragma unroll
                for (int j = 0; j < 4; ++j) {
                    const int jj = j >> 1, ss = j & 1;
                    mma16816(acc[i][j], Ah[i], Bh[jj][ss], Bh[jj][ss + 2]);
                    mma16816(acc[i][j], Ah[i], Bl[jj][ss], Bl[jj][ss + 2]);
                    mma16816(acc[i][j], Al[i], Bh[jj][ss], Bh[jj][ss + 2]);
                }
        }
        if (more) {
            char* base = sm + ((c + 1) & 1) * 4 * PLB;
#pragma unroll
            for (int i = 0; i < 8; ++i) {
                const int r = r0 + i * 16;
                const uint32_t off = (uint32_t)(r * KPAD + (c4 << 2)) * 2;
                uint32_t h01, h23, l01, l23;
                bf16x3_split(ra[i], h01, h23, l01, l23);
                *(uint2*)(base + off)       = make_uint2(h01, h23);
                *(uint2*)(base + PLB + off) = make_uint2(l01, l23);
                bf16x3_split(rb[i], h01, h23, l01, l23);
                *(uint2*)(base + 2 * PLB + off) = make_uint2(h01, h23);
                *(uint2*)(base + 3 * PLB + off) = make_uint2(l01, l23);
            }
        }
        __syncthreads();
    }

    const int g  = lane >> 2;
    const int tq = lane & 3;
#pragma unroll
    for (int i = 0; i < 4; ++i)
#pragma unroll
        for (int j = 0; j < 4; ++j) {
            const int row = bm0 + wm * 64 + i * 16 + g;
            const int col = bn0 + wn * 32 + j * 8 + tq * 2;
#pragma unroll
            for (int h = 0; h < 2; ++h) {
                const int rr = row + h * 8;
                float v0 = acc[i][j][h * 2 + 0];
                float v1 = acc[i][j][h * 2 + 1];
                if (BIAS) { v0 += bias[col]; v1 += bias[col + 1]; }
                if (CT_OUT) {
                    Cb[(long long)col * ldc + rr]       = v0;
                    Cb[(long long)(col + 1) * ldc + rr] = v1;
                } else {
                    float* cp = Cb + (long long)rr * ldc + col;
                    if (ACCUM) { v0 += cp[0]; v1 += cp[1]; }
                    cp[0] = v0; cp[1] = v1;
                }
            }
        }
}

// ======================= mega kernel: attn2(MMA)+softmax+values2(MMA) =======================
constexpr int TPAD = 136;                       // bf16 per plane row
constexpr int WSS  = 1032;                      // w_s fp32 row stride
constexpr int OFF_QH = 66048, OFF_QL = 70400, OFF_KH = 74752, OFF_KL = 109568;
constexpr int SMEM_MEGA = 144384;

__global__ void __launch_bounds__(256, 1)
mega_kernel(const float* __restrict__ q, const float* __restrict__ kb,
            const float* __restrict__ vb, const int* __restrict__ mask,
            float* __restrict__ scores, float* __restrict__ out)
{
    extern __shared__ char sm[];
    const uint32_t sb = smem_u32(sm);
    float* w_s = (float*)sm;
    const int s = blockIdx.x, tid = threadIdx.x;
    const int lane = tid & 31, wid = tid >> 5;
    const int lrow = lane & 15, lk = (lane >> 4) << 3;
    const int g = lane >> 2, tq = lane & 3;

    // q[:, s, :] -> bf16 hi/lo planes
#pragma unroll
    for (int i = 0; i < 2; ++i) {
        int f = tid + i * 256, b = f >> 5, d4 = (f & 31) << 2;
        float4 v = *(const float4*)&q[((long long)b * Sq + s) * Dd + d4];
        uint32_t h01, h23, l01, l23; bf16x3_split(v, h01, h23, l01, l23);
        uint32_t o = (uint32_t)(b * TPAD + d4) * 2;
        *(uint2*)(sm + OFF_QH + o) = make_uint2(h01, h23);
        *(uint2*)(sm + OFF_QL + o) = make_uint2(l01, l23);
    }
    __syncthreads();
    uint32_t Ah[8][4], Al[8][4];
#pragma unroll
    for (int ks = 0; ks < 8; ++ks) {
        uint32_t ro = (uint32_t)(lrow * TPAD + ks * 16 + lk) * 2;
        ldsm4(sb + OFF_QH + ro, Ah[ks]);
        ldsm4(sb + OFF_QL + ro, Al[ks]);
    }

    // ---- phase 1: w2 = q @ k_bias[s]^T  (n = t, k = d) ----
    float4 pf[16];
    const float* kbs = kb + (long long)s * Sq * Dd;
#pragma unroll
    for (int i = 0; i < 16; ++i) {
        int f = tid + i * 256, tt = f >> 5, d4 = (f & 31) << 2;
        pf[i] = *(const float4*)&kbs[(long long)tt * Dd + d4];
    }
    for (int c = 0; c < 8; ++c) {
#pragma unroll
        for (int i = 0; i < 16; ++i) {
            int f = tid + i * 256, tt = f >> 5, d4 = (f & 31) << 2;
            uint32_t h01, h23, l01, l23; bf16x3_split(pf[i], h01, h23, l01, l23);
            uint32_t o = (uint32_t)(tt * TPAD + d4) * 2;
            *(uint2*)(sm + OFF_KH + o) = make_uint2(h01, h23);
            *(uint2*)(sm + OFF_KL + o) = make_uint2(l01, l23);
        }
        __syncthreads();
        if (c < 7) {
            const float* nx = kbs + (long long)(c + 1) * 128 * Dd;
#pragma unroll
            for (int i = 0; i < 16; ++i) {
                int f = tid + i * 256, tt = f >> 5, d4 = (f & 31) << 2;
                pf[i] = *(const float4*)&nx[(long long)tt * Dd + d4];
            }
        }
        float acc2[2][4] = {};
#pragma unroll
        for (int ks = 0; ks < 8; ++ks) {
            uint32_t Bh[4], Bl[4];
            uint32_t ro = (uint32_t)((wid * 16 + lrow) * TPAD + ks * 16 + lk) * 2;
            ldsm4(sb + OFF_KH + ro, Bh); ldsm4(sb + OFF_KL + ro, Bl);
            mma16816(acc2[0], Ah[ks], Bh[0], Bh[2]);
            mma16816(acc2[0], Ah[ks], Bl[0], Bl[2]);
            mma16816(acc2[0], Al[ks], Bh[0], Bh[2]);
            mma16816(acc2[1], Ah[ks], Bh[1], Bh[3]);
            mma16816(acc2[1], Ah[ks], Bl[1], Bl[3]);
            mma16816(acc2[1], Al[ks], Bh[1], Bh[3]);
        }
#pragma unroll
        for (int j = 0; j < 2; ++j) {
            int col = c * 128 + wid * 16 + j * 8 + tq * 2;
            w_s[g * WSS + col]           = acc2[j][0];
            w_s[g * WSS + col + 1]       = acc2[j][1];
            w_s[(g + 8) * WSS + col]     = acc2[j][2];
            w_s[(g + 8) * WSS + col + 1] = acc2[j][3];
        }
        __syncthreads();
    }

    // prefetch v_bias chunk0 (overlaps softmax)
    const float* vbs = vb + (long long)s * Sq * Dd;
#pragma unroll
    for (int i = 0; i < 16; ++i) {
        int f = tid + i * 256, tt = f >> 5, d4 = (f & 31) << 2;
        pf[i] = *(const float4*)&vbs[(long long)tt * Dd + d4];
    }

    // ---- phase 2: softmax of (scores + w2)*scale with mask; warp wid rows 2wid,2wid+1 ----
    const float scale = 0.08838834764831845f;
#pragma unroll 1
    for (int r = 0; r < 2; ++r) {
        const int bb = wid * 2 + r;
        float* wrow = &w_s[bb * WSS];
        const long long gbase = ((long long)bb * Sq + s) * (long long)Sq;
        float4 vals[8]; float mx = -3e38f;
#pragma unroll
        for (int j2 = 0; j2 < 8; ++j2) {
            int t4 = lane + j2 * 32;
            float4 gsc = *(const float4*)&scores[gbase + t4 * 4];
            float4 ww  = *(const float4*)&wrow[t4 * 4];
            int4   mk  = *(const int4*)&mask[bb * Sq + t4 * 4];
            float4 v;
            v.x = (gsc.x + ww.x) * scale; if (!mk.x) v.x = -1e9f;
            v.y = (gsc.y + ww.y) * scale; if (!mk.y) v.y = -1e9f;
            v.z = (gsc.z + ww.z) * scale; if (!mk.z) v.z = -1e9f;
            v.w = (gsc.w + ww.w) * scale; if (!mk.w) v.w = -1e9f;
            vals[j2] = v;
            mx = fmaxf(mx, fmaxf(fmaxf(v.x, v.y), fmaxf(v.z, v.w)));
        }
#pragma unroll
        for (int o = 16; o > 0; o >>= 1) mx = fmaxf(mx, __shfl_xor_sync(0xffffffffu, mx, o));
        float sum = 0.f;
#pragma unroll
        for (int j2 = 0; j2 < 8; ++j2) {
            float4 v = vals[j2];
            v.x = __expf(v.x - mx); v.y = __expf(v.y - mx);
            v.z = __expf(v.z - mx); v.w = __expf(v.w - mx);
            vals[j2] = v;
            sum += v.x + v.y + v.z + v.w;
        }
#pragma unroll
        for (int o = 16; o > 0; o >>= 1) sum += __shfl_xor_sync(0xffffffffu, sum, o);
        const float inv = 1.0f / sum;
#pragma unroll
        for (int j2 = 0; j2 < 8; ++j2) {
            int t4 = lane + j2 * 32;
            float4 v = vals[j2];
            v.x *= inv; v.y *= inv; v.z *= inv; v.w *= inv;
            *(float4*)&scores[gbase + t4 * 4] = v;   // for values1
            *(float4*)&wrow[t4 * 4] = v;             // for phase 3
        }
    }
    __syncthreads();

    // ---- phase 3: out2 = w @ v_bias[s]  (n = d, k = t; B via ldmatrix.trans) ----
    float acc3[2][4] = {};
    for (int c = 0; c < 8; ++c) {
#pragma unroll
        for (int i = 0; i < 16; ++i) {
            int f = tid + i * 256, tt = f >> 5, d4 = (f & 31) << 2;
            uint32_t h01, h23, l01, l23; bf16x3_split(pf[i], h01, h23, l01, l23);
            uint32_t o = (uint32_t)(tt * TPAD + d4) * 2;
            *(uint2*)(sm + OFF_KH + o) = make_uint2(h01, h23);
            *(uint2*)(sm + OFF_KL + o) = make_uint2(l01, l23);
        }
        __syncthreads();
        if (c < 7) {
            const float* nx = vbs + (long long)(c + 1) * 128 * Dd;
#pragma unroll
            for (int i = 0; i < 16; ++i) {
                int f = tid + i * 256, tt = f >> 5, d4 = (f & 31) << 2;
                pf[i] = *(const float4*)&nx[(long long)tt * Dd + d4];
            }
        }
#pragma unroll
        for (int ks = 0; ks < 8; ++ks) {
            const int kk = c * 128 + ks * 16 + tq * 2;
            float2 x0 = *(const float2*)&w_s[g * WSS + kk];
            float2 x1 = *(const float2*)&w_s[(g + 8) * WSS + kk];
            float2 x2 = *(const float2*)&w_s[g * WSS + kk + 8];
            float2 x3 = *(const float2*)&w_s[(g + 8) * WSS + kk + 8];
            uint32_t A2h[4], A2l[4];
            split2(x0, A2h[0], A2l[0]); split2(x1, A2h[1], A2l[1]);
            split2(x2, A2h[2], A2l[2]); split2(x3, A2h[3], A2l[3]);
            uint32_t Bh[4], Bl[4];
            uint32_t ro = (uint32_t)((ks * 16 + lrow) * TPAD + wid * 16 + lk) * 2;
            ldsm4t(sb + OFF_KH + ro, Bh); ldsm4t(sb + OFF_KL + ro, Bl);
            mma16816(acc3[0], A2h, Bh[0], Bh[1]);
            mma16816(acc3[0], A2h, Bl[0], Bl[1]);
            mma16816(acc3[0], A2l, Bh[0], Bh[1]);
            mma16816(acc3[1], A2h, Bh[2], Bh[3]);
            mma16816(acc3[1], A2h, Bl[2], Bl[3]);
            mma16816(acc3[1], A2l, Bh[2], Bh[3]);
        }
        __syncthreads();
    }
#pragma unroll
    for (int j = 0; j < 2; ++j) {
        const int d = wid * 16 + j * 8 + tq * 2;
        out[((long long)g * Sq + s) * Dd + d]           = acc3[j][0];
        out[((long long)g * Sq + s) * Dd + d + 1]       = acc3[j][1];
        out[((long long)(g + 8) * Sq + s) * Dd + d]     = acc3[j][2];
        out[((long long)(g + 8) * Sq + s) * Dd + d + 1] = acc3[j][3];
    }
}

// ======================= launch =======================
extern "C" void kernel_launch(void* const* d_in, const int* in_sizes, int n_in,
                              void* d_out, int out_size)
{
    const float* query  = (const float*)d_in[0];
    const float* key_   = (const float*)d_in[1];
    const float* value  = (const float*)d_in[2];
    const int*   mask   = (const int*)  d_in[3];
    const float* Wq     = (const float*)d_in[4];
    const float* bq     = (const float*)d_in[5];
    const float* Wk     = (const float*)d_in[6];
    const float* bk     = (const float*)d_in[7];
    const float* Wv     = (const float*)d_in[8];
    const float* bv     = (const float*)d_in[9];
    const float* k_bias = (const float*)d_in[10];
    const float* v_bias = (const float*)d_in[11];
    float* out = (float*)d_out;

    void *pq, *pk, *pv, *ps;
    cudaGetSymbolAddress(&pq, g_q);
    cudaGetSymbolAddress(&pk, g_k);
    cudaGetSymbolAddress(&pv, g_vT);
    cudaGetSymbolAddress(&ps, g_scores);
    float* q  = (float*)pq;
    float* k  = (float*)pk;
    float* vT = (float*)pv;
    float* sc = (float*)ps;

    cudaFuncSetAttribute(mma_gemm_kernel<true,  false, false>,
                         cudaFuncAttributeMaxDynamicSharedMemorySize, SMEM_GEMM);
    cudaFuncSetAttribute(mma_gemm_kernel<true,  false, true>,
                         cudaFuncAttributeMaxDynamicSharedMemorySize, SMEM_GEMM);
    cudaFuncSetAttribute(mma_gemm_kernel<false, false, false>,
                         cudaFuncAttributeMaxDynamicSharedMemorySize, SMEM_GEMM);
    cudaFuncSetAttribute(mma_gemm_kernel<false, true,  false>,
                         cudaFuncAttributeMaxDynamicSharedMemorySize, SMEM_GEMM);
    cudaFuncSetAttribute(mega_kernel,
                         cudaFuncAttributeMaxDynamicSharedMemorySize, SMEM_MEGA);

    dim3 blk(256);
    dim3 gp(1, (Bsz * Sq) / 128, 1);
    mma_gemm_kernel<true, false, false><<<gp, blk, SMEM_GEMM>>>(
        query, Wq, bq, q, Hd, Hd, Hd, Dd, 0, 0, 0);
    mma_gemm_kernel<true, false, false><<<gp, blk, SMEM_GEMM>>>(
        key_,  Wk, bk, k, Hd, Hd, Hd, Dd, 0, 0, 0);
    mma_gemm_kernel<true, false, true><<<gp, blk, SMEM_GEMM>>>(
        value, Wv, bv, vT, Hd, Hd, Hd, Bsz * Sq, 0, 0, 0);

    dim3 g1(Sq / 128, Sq / 128, Bsz);
    mma_gemm_kernel<false, false, false><<<g1, blk, SMEM_GEMM>>>(
        q, k, nullptr, sc, Dd, Dd, Dd, Sq,
        (long long)Sq * Dd, (long long)Sq * Dd, (long long)Sq * Sq);

    mega_kernel<<<Sq, blk, SMEM_MEGA>>>(q, k_bias, v_bias, mask, sc, out);

    dim3 g6(Dd / 128, Sq / 128, Bsz);
    mma_gemm_kernel<false, true, false><<<g6, blk, SMEM_GEMM>>>(
        sc, vT, nullptr, out, Sq, Sq, Bsz * Sq, Dd,
        (long long)Sq * Sq, (long long)Sq, (long long)Sq * Dd);
}

// round 7
// speedup vs baseline: 2.5011x; 1.0178x over previous
#include <cuda_runtime.h>
#include <cuda_bf16.h>
#include <cstdint>

constexpr int Bsz = 16;
constexpr int Sq  = 1024;
constexpr int Hd  = 1024;
constexpr int Dd  = 128;

// Pre-split bf16 hi/lo planes (bf16x3 decomposition storage)
__device__ uint16_t g_qh[Bsz * Sq * Dd], g_ql[Bsz * Sq * Dd];
__device__ uint16_t g_kh[Bsz * Sq * Dd], g_kl[Bsz * Sq * Dd];
__device__ uint16_t g_vTh[Dd * Bsz * Sq], g_vTl[Dd * Bsz * Sq];   // vT[d][b*S+t]
__device__ uint16_t g_wh[(size_t)Bsz * Sq * Sq], g_wl[(size_t)Bsz * Sq * Sq];
__device__ float    g_scores[(size_t)Bsz * Sq * Sq];

// ======================= helpers =======================
__device__ __forceinline__ uint32_t smem_u32(const void* p) {
    uint32_t a;
    asm("{ .reg .u64 t; cvta.to.shared.u64 t, %1; cvt.u32.u64 %0, t; }" : "=r"(a) : "l"(p));
    return a;
}
__device__ __forceinline__ void ldsm4(uint32_t addr, uint32_t* r) {
    asm volatile("ldmatrix.sync.aligned.m8n8.x4.shared.b16 {%0,%1,%2,%3}, [%4];"
                 : "=r"(r[0]), "=r"(r[1]), "=r"(r[2]), "=r"(r[3]) : "r"(addr));
}
__device__ __forceinline__ void ldsm4t(uint32_t addr, uint32_t* r) {
    asm volatile("ldmatrix.sync.aligned.m8n8.x4.trans.shared.b16 {%0,%1,%2,%3}, [%4];"
                 : "=r"(r[0]), "=r"(r[1]), "=r"(r[2]), "=r"(r[3]) : "r"(addr));
}
__device__ __forceinline__ void mma16816(float* c, const uint32_t* a, uint32_t b0, uint32_t b1) {
    asm volatile(
        "mma.sync.aligned.m16n8k16.row.col.f32.bf16.bf16.f32 "
        "{%0,%1,%2,%3}, {%4,%5,%6,%7}, {%8,%9}, {%0,%1,%2,%3};"
        : "+f"(c[0]), "+f"(c[1]), "+f"(c[2]), "+f"(c[3])
        : "r"(a[0]), "r"(a[1]), "r"(a[2]), "r"(a[3]), "r"(b0), "r"(b1));
}
__device__ __forceinline__ void bf16x3_split(float4 v, uint32_t& h01, uint32_t& h23,
                                             uint32_t& l01, uint32_t& l23) {
    asm("cvt.rn.bf16x2.f32 %0, %1, %2;" : "=r"(h01) : "f"(v.y), "f"(v.x));
    asm("cvt.rn.bf16x2.f32 %0, %1, %2;" : "=r"(h23) : "f"(v.w), "f"(v.z));
    float h0 = __uint_as_float(h01 << 16);
    float h1 = __uint_as_float(h01 & 0xffff0000u);
    float h2 = __uint_as_float(h23 << 16);
    float h3 = __uint_as_float(h23 & 0xffff0000u);
    float l0 = v.x - h0, l1 = v.y - h1, l2 = v.z - h2, l3 = v.w - h3;
    asm("cvt.rn.bf16x2.f32 %0, %1, %2;" : "=r"(l01) : "f"(l1), "f"(l0));
    asm("cvt.rn.bf16x2.f32 %0, %1, %2;" : "=r"(l23) : "f"(l3), "f"(l2));
}
__device__ __forceinline__ void split2(float2 v, uint32_t& h, uint32_t& l) {
    asm("cvt.rn.bf16x2.f32 %0, %1, %2;" : "=r"(h) : "f"(v.y), "f"(v.x));
    float h0 = __uint_as_float(h << 16);
    float h1 = __uint_as_float(h & 0xffff0000u);
    float l0 = v.x - h0, l1 = v.y - h1;
    asm("cvt.rn.bf16x2.f32 %0, %1, %2;" : "=r"(l) : "f"(l1), "f"(l0));
}

constexpr int KPAD = 72;
constexpr int PLB  = 128 * KPAD * 2;          // 18432 B per plane
constexpr int SMEM_GEMM = 8 * PLB;            // 147456 B

// ======================= fused projection kernel (fp32 in, split bf16 out) =======================
// z=0: q = query@Wq^T+bq -> g_qh/g_ql;  z=1: k -> g_kh/g_kl;  z=2: v -> g_vTh/g_vTl (transposed)
__global__ void __launch_bounds__(256, 1)
proj_kernel(const float* __restrict__ query, const float* __restrict__ key_,
            const float* __restrict__ value,
            const float* __restrict__ Wq, const float* __restrict__ bq,
            const float* __restrict__ Wk, const float* __restrict__ bk,
            const float* __restrict__ Wv, const float* __restrict__ bv)
{
    extern __shared__ char sm[];
    const uint32_t sb = smem_u32(sm);
    const int tid = threadIdx.x, lane = tid & 31, wid = tid >> 5;
    const int wm = wid >> 2, wn = wid & 3;
    const int z = blockIdx.z;
    const int bm0 = blockIdx.y * 128;

    const float *A, *Bw, *bias;
    if (z == 0)      { A = query; Bw = Wq; bias = bq; }
    else if (z == 1) { A = key_;  Bw = Wk; bias = bk; }
    else             { A = value; Bw = Wv; bias = bv; }
    const float* Ab = A + (long long)bm0 * Hd;

    float acc[4][4][4];
#pragma unroll
    for (int i = 0; i < 4; ++i)
#pragma unroll
        for (int j = 0; j < 4; ++j)
#pragma unroll
            for (int r = 0; r < 4; ++r) acc[i][j][r] = 0.f;

    const int r0 = tid >> 4;
    const int c4 = tid & 15;
    const int nch = Hd >> 6;   // 16

    float4 ra[8], rb[8];
#pragma unroll
    for (int i = 0; i < 8; ++i) {
        const int r = r0 + i * 16;
        ra[i] = *(const float4*)(Ab + (long long)r * Hd + (c4 << 2));
        rb[i] = *(const float4*)(Bw + (long long)r * Hd + (c4 << 2));
    }
    {
        char* base = sm;
#pragma unroll
        for (int i = 0; i < 8; ++i) {
            const int r = r0 + i * 16;
            const uint32_t off = (uint32_t)(r * KPAD + (c4 << 2)) * 2;
            uint32_t h01, h23, l01, l23;
            bf16x3_split(ra[i], h01, h23, l01, l23);
            *(uint2*)(base + off)       = make_uint2(h01, h23);
            *(uint2*)(base + PLB + off) = make_uint2(l01, l23);
            bf16x3_split(rb[i], h01, h23, l01, l23);
            *(uint2*)(base + 2 * PLB + off) = make_uint2(h01, h23);
            *(uint2*)(base + 3 * PLB + off) = make_uint2(l01, l23);
        }
    }
    __syncthreads();

    const int lrow = lane & 15;
    const int lk   = (lane >> 4) << 3;

    for (int c = 0; c < nch; ++c) {
        const bool more = (c + 1) < nch;
        if (more) {
            const float* Ac = Ab + (c + 1) * 64;
            const float* Bc = Bw + (c + 1) * 64;
#pragma unroll
            for (int i = 0; i < 8; ++i) {
                const int r = r0 + i * 16;
                ra[i] = *(const float4*)(Ac + (long long)r * Hd + (c4 << 2));
                rb[i] = *(const float4*)(Bc + (long long)r * Hd + (c4 << 2));
            }
        }
        const uint32_t bo = (uint32_t)(c & 1) * 4u * PLB;
#pragma unroll
        for (int ks = 0; ks < 4; ++ks) {
            const int k0 = ks * 16;
            uint32_t Ah[4][4], Al[4][4], Bh[2][4], Bl[2][4];
#pragma unroll
            for (int i = 0; i < 4; ++i) {
                const uint32_t ro = (uint32_t)((wm * 64 + i * 16 + lrow) * KPAD + k0 + lk) * 2;
                ldsm4(sb + bo + ro, Ah[i]);
                ldsm4(sb + bo + PLB + ro, Al[i]);
            }
#pragma unroll
            for (int jj = 0; jj < 2; ++jj) {
                const uint32_t ro = (uint32_t)((wn * 32 + jj * 16 + lrow) * KPAD + k0 + lk) * 2;
                ldsm4(sb + bo + 2 * PLB + ro, Bh[jj]);
                ldsm4(sb + bo + 3 * PLB + ro, Bl[jj]);
            }
#pragma unroll
            for (int i = 0; i < 4; ++i)
#pragma unroll
                for (int j = 0; j < 4; ++j) {
                    const int jj = j >> 1, ss = j & 1;
                    mma16816(acc[i][j], Ah[i], Bh[jj][ss], Bh[jj][ss + 2]);
                    mma16816(acc[i][j], Ah[i], Bl[jj][ss], Bl[jj][ss + 2]);
                    mma16816(acc[i][j], Al[i], Bh[jj][ss], Bh[jj][ss + 2]);
                }
        }
        if (more) {
            char* base = sm + ((c + 1) & 1) * 4 * PLB;
#pragma unroll
            for (int i = 0; i < 8; ++i) {
                const int r = r0 + i * 16;
                const uint32_t off = (uint32_t)(r * KPAD + (c4 << 2)) * 2;
                uint32_t h01, h23, l01, l23;
                bf16x3_split(ra[i], h01, h23, l01, l23);
                *(uint2*)(base + off)       = make_uint2(h01, h23);
                *(uint2*)(base + PLB + off) = make_uint2(l01, l23);
                bf16x3_split(rb[i], h01, h23, l01, l23);
                *(uint2*)(base + 2 * PLB + off) = make_uint2(h01, h23);
                *(uint2*)(base + 3 * PLB + off) = make_uint2(l01, l23);
            }
        }
        __syncthreads();
    }

    // epilogue: +bias, split to bf16 hi/lo planes
    uint16_t *Oh, *Ol;
    if (z == 0)      { Oh = g_qh;  Ol = g_ql; }
    else if (z == 1) { Oh = g_kh;  Ol = g_kl; }
    else             { Oh = g_vTh; Ol = g_vTl; }
    const int g  = lane >> 2;
    const int tq = lane & 3;
#pragma unroll
    for (int i = 0; i < 4; ++i)
#pragma unroll
        for (int j = 0; j < 4; ++j) {
            const int row = bm0 + wm * 64 + i * 16 + g;
            const int col = wn * 32 + j * 8 + tq * 2;
#pragma unroll
            for (int h = 0; h < 2; ++h) {
                const int rr = row + h * 8;
                float v0 = acc[i][j][h * 2 + 0] + bias[col];
                float v1 = acc[i][j][h * 2 + 1] + bias[col + 1];
                uint32_t hh, ll;
                split2(make_float2(v0, v1), hh, ll);
                if (z < 2) {
                    *(uint32_t*)&Oh[(size_t)rr * Dd + col] = hh;
                    *(uint32_t*)&Ol[(size_t)rr * Dd + col] = ll;
                } else {
                    Oh[(size_t)col * (Bsz * Sq) + rr]       = (uint16_t)(hh & 0xffff);
                    Oh[(size_t)(col + 1) * (Bsz * Sq) + rr] = (uint16_t)(hh >> 16);
                    Ol[(size_t)col * (Bsz * Sq) + rr]       = (uint16_t)(ll & 0xffff);
                    Ol[(size_t)(col + 1) * (Bsz * Sq) + rr] = (uint16_t)(ll >> 16);
                }
            }
        }
}

// ======================= bf16-input GEMM (pre-split planes) =======================
// C[128x128] per CTA.  A planes: [M,K] lda (K-contig).  B planes: [N,K] ldb.  D=A@B^T.
template<bool ACCUM>
__global__ void __launch_bounds__(256, 1)
bf16_gemm_kernel(const uint16_t* __restrict__ Ah_, const uint16_t* __restrict__ Al_,
                 const uint16_t* __restrict__ Bh_, const uint16_t* __restrict__ Bl_,
                 float* __restrict__ C_, int K, int lda, int ldb, int ldc,
                 long long aO, long long bO, long long cO)
{
    extern __shared__ char sm[];
    const uint32_t sb = smem_u32(sm);
    const int tid = threadIdx.x, lane = tid & 31, wid = tid >> 5;
    const int wm = wid >> 2, wn = wid & 3;
    const int bn0 = blockIdx.x * 128;
    const int bm0 = blockIdx.y * 128;
    const long long z = blockIdx.z;
    const uint16_t* Ah = Ah_ + z * aO + (long long)bm0 * lda;
    const uint16_t* Al = Al_ + z * aO + (long long)bm0 * lda;
    const uint16_t* Bh = Bh_ + z * bO + (long long)bn0 * ldb;
    const uint16_t* Bl = Bl_ + z * bO + (long long)bn0 * ldb;
    float* C = C_ + z * cO;

    float acc[4][4][4];
#pragma unroll
    for (int i = 0; i < 4; ++i)
#pragma unroll
        for (int j = 0; j < 4; ++j)
#pragma unroll
            for (int r = 0; r < 4; ++r) acc[i][j][r] = 0.f;

    // copy mapping: 8 threads per 128B plane-row segment
    const int c8 = tid & 7;          // uint4 within row (16B units)
    const int r0 = tid >> 3;         // rows r0 + 32*i
    const int nch = K >> 6;

    uint4 pre[4][4];
#pragma unroll
    for (int i = 0; i < 4; ++i) {
        const int r = r0 + i * 32;
        pre[0][i] = *(const uint4*)&Ah[(long long)r * lda + c8 * 8];
        pre[1][i] = *(const uint4*)&Al[(long long)r * lda + c8 * 8];
        pre[2][i] = *(const uint4*)&Bh[(long long)r * ldb + c8 * 8];
        pre[3][i] = *(const uint4*)&Bl[(long long)r * ldb + c8 * 8];
    }
    {
        char* base = sm;
#pragma unroll
        for (int i = 0; i < 4; ++i) {
            const uint32_t off = (uint32_t)((r0 + i * 32) * 144 + c8 * 16);
            *(uint4*)(base + off)           = pre[0][i];
            *(uint4*)(base + PLB + off)     = pre[1][i];
            *(uint4*)(base + 2 * PLB + off) = pre[2][i];
            *(uint4*)(base + 3 * PLB + off) = pre[3][i];
        }
    }
    __syncthreads();

    const int lrow = lane & 15;
    const int lk   = (lane >> 4) << 3;

    for (int c = 0; c < nch; ++c) {
        const bool more = (c + 1) < nch;
        if (more) {
            const int ko = (c + 1) * 64;
#pragma unroll
            for (int i = 0; i < 4; ++i) {
                const int r = r0 + i * 32;
                pre[0][i] = *(const uint4*)&Ah[(long long)r * lda + ko + c8 * 8];
                pre[1][i] = *(const uint4*)&Al[(long long)r * lda + ko + c8 * 8];
                pre[2][i] = *(const uint4*)&Bh[(long long)r * ldb + ko + c8 * 8];
                pre[3][i] = *(const uint4*)&Bl[(long long)r * ldb + ko + c8 * 8];
            }
        }
        const uint32_t bo = (uint32_t)(c & 1) * 4u * PLB;
#pragma unroll
        for (int ks = 0; ks < 4; ++ks) {
            const int k0 = ks * 16;
            uint32_t Af[4][4], Af2[4][4], Bf[2][4], Bf2[2][4];
#pragma unroll
            for (int i = 0; i < 4; ++i) {
                const uint32_t ro = (uint32_t)((wm * 64 + i * 16 + lrow) * KPAD + k0 + lk) * 2;
                ldsm4(sb + bo + ro, Af[i]);
                ldsm4(sb + bo + PLB + ro, Af2[i]);
            }
#pragma unroll
            for (int jj = 0; jj < 2; ++jj) {
                const uint32_t ro = (uint32_t)((wn * 32 + jj * 16 + lrow) * KPAD + k0 + lk) * 2;
                ldsm4(sb + bo + 2 * PLB + ro, Bf[jj]);
                ldsm4(sb + bo + 3 * PLB + ro, Bf2[jj]);
            }
#pragma unroll
            for (int i = 0; i < 4; ++i)
#pragma unroll
                for (int j = 0; j < 4; ++j) {
                    const int jj = j >> 1, ss = j & 1;
                    mma16816(acc[i][j], Af[i],  Bf[jj][ss],  Bf[jj][ss + 2]);
                    mma16816(acc[i][j], Af[i],  Bf2[jj][ss], Bf2[jj][ss + 2]);
                    mma16816(acc[i][j], Af2[i], Bf[jj][ss],  Bf[jj][ss + 2]);
                }
        }
        if (more) {
            char* base = sm + ((c + 1) & 1) * 4 * PLB;
#pragma unroll
            for (int i = 0; i < 4; ++i) {
                const uint32_t off = (uint32_t)((r0 + i * 32) * 144 + c8 * 16);
                *(uint4*)(base + off)           = pre[0][i];
                *(uint4*)(base + PLB + off)     = pre[1][i];
                *(uint4*)(base + 2 * PLB + off) = pre[2][i];
                *(uint4*)(base + 3 * PLB + off) = pre[3][i];
            }
        }
        __syncthreads();
    }

    const int g  = lane >> 2;
    const int tq = lane & 3;
#pragma unroll
    for (int i = 0; i < 4; ++i)
#pragma unroll
        for (int j = 0; j < 4; ++j) {
            const int row = bm0 + wm * 64 + i * 16 + g;
            const int col = bn0 + wn * 32 + j * 8 + tq * 2;
#pragma unroll
            for (int h = 0; h < 2; ++h) {
                const int rr = row + h * 8;
                float v0 = acc[i][j][h * 2 + 0];
                float v1 = acc[i][j][h * 2 + 1];
                float* cp = C + (long long)rr * ldc + col;
                if (ACCUM) { v0 += cp[0]; v1 += cp[1]; }
                cp[0] = v0; cp[1] = v1;
            }
        }
}

// ======================= mega kernel: attn2(MMA)+softmax+values2(MMA) =======================
constexpr int TPAD = 136;
constexpr int WSS  = 1032;
constexpr int OFF_QH = 66048, OFF_QL = 70400, OFF_KH = 74752, OFF_KL = 109568;
constexpr int SMEM_MEGA = 144384;

__global__ void __launch_bounds__(256, 1)
mega_kernel(const float* __restrict__ kb, const float* __restrict__ vb,
            const int* __restrict__ mask, const float* __restrict__ scores,
            float* __restrict__ out)
{
    extern __shared__ char sm[];
    const uint32_t sb = smem_u32(sm);
    float* w_s = (float*)sm;
    const int s = blockIdx.x, tid = threadIdx.x;
    const int lane = tid & 31, wid = tid >> 5;
    const int lrow = lane & 15, lk = (lane >> 4) << 3;
    const int g = lane >> 2, tq = lane & 3;

    // q[:, s, :] from pre-split planes
#pragma unroll
    for (int i = 0; i < 2; ++i) {
        int f = tid + i * 256, b = f >> 5, d4 = (f & 31) << 2;
        uint2 hv = *(const uint2*)&g_qh[((size_t)b * Sq + s) * Dd + d4];
        uint2 lv = *(const uint2*)&g_ql[((size_t)b * Sq + s) * Dd + d4];
        uint32_t o = (uint32_t)(b * TPAD + d4) * 2;
        *(uint2*)(sm + OFF_QH + o) = hv;
        *(uint2*)(sm + OFF_QL + o) = lv;
    }
    __syncthreads();
    uint32_t Ah[8][4], Al[8][4];
#pragma unroll
    for (int ks = 0; ks < 8; ++ks) {
        uint32_t ro = (uint32_t)(lrow * TPAD + ks * 16 + lk) * 2;
        ldsm4(sb + OFF_QH + ro, Ah[ks]);
        ldsm4(sb + OFF_QL + ro, Al[ks]);
    }

    // ---- phase 1: w2 = q @ k_bias[s]^T ----
    float4 pf[16];
    const float* kbs = kb + (long long)s * Sq * Dd;
#pragma unroll
    for (int i = 0; i < 16; ++i) {
        int f = tid + i * 256, tt = f >> 5, d4 = (f & 31) << 2;
        pf[i] = *(const float4*)&kbs[(long long)tt * Dd + d4];
    }
    for (int c = 0; c < 8; ++c) {
#pragma unroll
        for (int i = 0; i < 16; ++i) {
            int f = tid + i * 256, tt = f >> 5, d4 = (f & 31) << 2;
            uint32_t h01, h23, l01, l23; bf16x3_split(pf[i], h01, h23, l01, l23);
            uint32_t o = (uint32_t)(tt * TPAD + d4) * 2;
            *(uint2*)(sm + OFF_KH + o) = make_uint2(h01, h23);
            *(uint2*)(sm + OFF_KL + o) = make_uint2(l01, l23);
        }
        __syncthreads();
        if (c < 7) {
            const float* nx = kbs + (long long)(c + 1) * 128 * Dd;
#pragma unroll
            for (int i = 0; i < 16; ++i) {
                int f = tid + i * 256, tt = f >> 5, d4 = (f & 31) << 2;
                pf[i] = *(const float4*)&nx[(long long)tt * Dd + d4];
            }
        }
        float acc2[2][4] = {};
#pragma unroll
        for (int ks = 0; ks < 8; ++ks) {
            uint32_t Bh[4], Bl[4];
            uint32_t ro = (uint32_t)((wid * 16 + lrow) * TPAD + ks * 16 + lk) * 2;
            ldsm4(sb + OFF_KH + ro, Bh); ldsm4(sb + OFF_KL + ro, Bl);
            mma16816(acc2[0], Ah[ks], Bh[0], Bh[2]);
            mma16816(acc2[0], Ah[ks], Bl[0], Bl[2]);
            mma16816(acc2[0], Al[ks], Bh[0], Bh[2]);
            mma16816(acc2[1], Ah[ks], Bh[1], Bh[3]);
            mma16816(acc2[1], Ah[ks], Bl[1], Bl[3]);
            mma16816(acc2[1], Al[ks], Bh[1], Bh[3]);
        }
#pragma unroll
        for (int j = 0; j < 2; ++j) {
            int col = c * 128 + wid * 16 + j * 8 + tq * 2;
            w_s[g * WSS + col]           = acc2[j][0];
            w_s[g * WSS + col + 1]       = acc2[j][1];
            w_s[(g + 8) * WSS + col]     = acc2[j][2];
            w_s[(g + 8) * WSS + col + 1] = acc2[j][3];
        }
        __syncthreads();
    }

    // prefetch v_bias chunk0
    const float* vbs = vb + (long long)s * Sq * Dd;
#pragma unroll
    for (int i = 0; i < 16; ++i) {
        int f = tid + i * 256, tt = f >> 5, d4 = (f & 31) << 2;
        pf[i] = *(const float4*)&vbs[(long long)tt * Dd + d4];
    }

    // ---- phase 2: softmax; w -> smem (fp32) + global bf16 hi/lo planes ----
    const float scale = 0.08838834764831845f;
#pragma unroll 1
    for (int r = 0; r < 2; ++r) {
        const int bb = wid * 2 + r;
        float* wrow = &w_s[bb * WSS];
        const long long gbase = ((long long)bb * Sq + s) * (long long)Sq;
        float4 vals[8]; float mx = -3e38f;
#pragma unroll
        for (int j2 = 0; j2 < 8; ++j2) {
            int t4 = lane + j2 * 32;
            float4 gsc = *(const float4*)&scores[gbase + t4 * 4];
            float4 ww  = *(const float4*)&wrow[t4 * 4];
            int4   mk  = *(const int4*)&mask[bb * Sq + t4 * 4];
            float4 v;
            v.x = (gsc.x + ww.x) * scale; if (!mk.x) v.x = -1e9f;
            v.y = (gsc.y + ww.y) * scale; if (!mk.y) v.y = -1e9f;
            v.z = (gsc.z + ww.z) * scale; if (!mk.z) v.z = -1e9f;
            v.w = (gsc.w + ww.w) * scale; if (!mk.w) v.w = -1e9f;
            vals[j2] = v;
            mx = fmaxf(mx, fmaxf(fmaxf(v.x, v.y), fmaxf(v.z, v.w)));
        }
#pragma unroll
        for (int o = 16; o > 0; o >>= 1) mx = fmaxf(mx, __shfl_xor_sync(0xffffffffu, mx, o));
        float sum = 0.f;
#pragma unroll
        for (int j2 = 0; j2 < 8; ++j2) {
            float4 v = vals[j2];
            v.x = __expf(v.x - mx); v.y = __expf(v.y - mx);
            v.z = __expf(v.z - mx); v.w = __expf(v.w - mx);
            vals[j2] = v;
            sum += v.x + v.y + v.z + v.w;
        }
#pragma unroll
        for (int o = 16; o > 0; o >>= 1) sum += __shfl_xor_sync(0xffffffffu, sum, o);
        const float inv = 1.0f / sum;
#pragma unroll
        for (int j2 = 0; j2 < 8; ++j2) {
            int t4 = lane + j2 * 32;
            float4 v = vals[j2];
            v.x *= inv; v.y *= inv; v.z *= inv; v.w *= inv;
            *(float4*)&wrow[t4 * 4] = v;
            uint32_t h0, l0, h1, l1;
            split2(make_float2(v.x, v.y), h0, l0);
            split2(make_float2(v.z, v.w), h1, l1);
            size_t we = (size_t)gbase + (size_t)t4 * 4;
            *(uint2*)&g_wh[we] = make_uint2(h0, h1);
            *(uint2*)&g_wl[we] = make_uint2(l0, l1);
        }
    }
    __syncthreads();

    // ---- phase 3: out2 = w @ v_bias[s] ----
    float acc3[2][4] = {};
    for (int c = 0; c < 8; ++c) {
#pragma unroll
        for (int i = 0; i < 16; ++i) {
            int f = tid + i * 256, tt = f >> 5, d4 = (f & 31) << 2;
            uint32_t h01, h23, l01, l23; bf16x3_split(pf[i], h01, h23, l01, l23);
            uint32_t o = (uint32_t)(tt * TPAD + d4) * 2;
            *(uint2*)(sm + OFF_KH + o) = make_uint2(h01, h23);
            *(uint2*)(sm + OFF_KL + o) = make_uint2(l01, l23);
        }
        __syncthreads();
        if (c < 7) {
            const float* nx = vbs + (long long)(c + 1) * 128 * Dd;
#pragma unroll
            for (int i = 0; i < 16; ++i) {
                int f = tid + i * 256, tt = f >> 5, d4 = (f & 31) << 2;
                pf[i] = *(const float4*)&nx[(long long)tt * Dd + d4];
            }
        }
#pragma unroll
        for (int ks = 0; ks < 8; ++ks) {
            const int kk = c * 128 + ks * 16 + tq * 2;
            float2 x0 = *(const float2*)&w_s[g * WSS + kk];
            float2 x1 = *(const float2*)&w_s[(g + 8) * WSS + kk];
            float2 x2 = *(const float2*)&w_s[g * WSS + kk + 8];
            float2 x3 = *(const float2*)&w_s[(g + 8) * WSS + kk + 8];
            uint32_t A2h[4], A2l[4];
            split2(x0, A2h[0], A2l[0]); split2(x1, A2h[1], A2l[1]);
            split2(x2, A2h[2], A2l[2]); split2(x3, A2h[3], A2l[3]);
            uint32_t Bh[4], Bl[4];
            uint32_t ro = (uint32_t)((ks * 16 + lrow) * TPAD + wid * 16 + lk) * 2;
            ldsm4t(sb + OFF_KH + ro, Bh); ldsm4t(sb + OFF_KL + ro, Bl);
            mma16816(acc3[0], A2h, Bh[0], Bh[1]);
            mma16816(acc3[0], A2h, Bl[0], Bl[1]);
            mma16816(acc3[0], A2l, Bh[0], Bh[1]);
            mma16816(acc3[1], A2h, Bh[2], Bh[3]);
            mma16816(acc3[1], A2h, Bl[2], Bl[3]);
            mma16816(acc3[1], A2l, Bh[2], Bh[3]);
        }
        __syncthreads();
    }
#pragma unroll
    for (int j = 0; j < 2; ++j) {
        const int d = wid * 16 + j * 8 + tq * 2;
        out[((long long)g * Sq + s) * Dd + d]           = acc3[j][0];
        out[((long long)g * Sq + s) * Dd + d + 1]       = acc3[j][1];
        out[((long long)(g + 8) * Sq + s) * Dd + d]     = acc3[j][2];
        out[((long long)(g + 8) * Sq + s) * Dd + d + 1] = acc3[j][3];
    }
}

// ======================= launch =======================
extern "C" void kernel_launch(void* const* d_in, const int* in_sizes, int n_in,
                              void* d_out, int out_size)
{
    const float* query  = (const float*)d_in[0];
    const float* key_   = (const float*)d_in[1];
    const float* value  = (const float*)d_in[2];
    const int*   mask   = (const int*)  d_in[3];
    const float* Wq     = (const float*)d_in[4];
    const float* bq     = (const float*)d_in[5];
    const float* Wk     = (const float*)d_in[6];
    const float* bk     = (const float*)d_in[7];
    const float* Wv     = (const float*)d_in[8];
    const float* bv     = (const float*)d_in[9];
    const float* k_bias = (const float*)d_in[10];
    const float* v_bias = (const float*)d_in[11];
    float* out = (float*)d_out;

    void *pqh, *pql, *pkh, *pkl, *pvh, *pvl, *pwh, *pwl, *ps;
    cudaGetSymbolAddress(&pqh, g_qh);  cudaGetSymbolAddress(&pql, g_ql);
    cudaGetSymbolAddress(&pkh, g_kh);  cudaGetSymbolAddress(&pkl, g_kl);
    cudaGetSymbolAddress(&pvh, g_vTh); cudaGetSymbolAddress(&pvl, g_vTl);
    cudaGetSymbolAddress(&pwh, g_wh);  cudaGetSymbolAddress(&pwl, g_wl);
    cudaGetSymbolAddress(&ps,  g_scores);
    float* sc = (float*)ps;

    cudaFuncSetAttribute(proj_kernel,
                         cudaFuncAttributeMaxDynamicSharedMemorySize, SMEM_GEMM);
    cudaFuncSetAttribute(bf16_gemm_kernel<false>,
                         cudaFuncAttributeMaxDynamicSharedMemorySize, SMEM_GEMM);
    cudaFuncSetAttribute(bf16_gemm_kernel<true>,
                         cudaFuncAttributeMaxDynamicSharedMemorySize, SMEM_GEMM);
    cudaFuncSetAttribute(mega_kernel,
                         cudaFuncAttributeMaxDynamicSharedMemorySize, SMEM_MEGA);

    dim3 blk(256);

    // fused projections: q, k, vT (grid.z selects)
    proj_kernel<<<dim3(1, 128, 3), blk, SMEM_GEMM>>>(
        query, key_, value, Wq, bq, Wk, bk, Wv, bv);

    // attn1: scores[b] = q[b] @ k[b]^T  (bf16 planes)
    bf16_gemm_kernel<false><<<dim3(8, 8, 16), blk, SMEM_GEMM>>>(
        (const uint16_t*)pqh, (const uint16_t*)pql,
        (const uint16_t*)pkh, (const uint16_t*)pkl,
        sc, Dd, Dd, Dd, Sq,
        (long long)Sq * Dd, (long long)Sq * Dd, (long long)Sq * Sq);

    // mega: attn2 + softmax (writes w planes) + values2 (writes out)
    mega_kernel<<<Sq, blk, SMEM_MEGA>>>(k_bias, v_bias, mask, sc, out);

    // values1: out += w[b] @ v[b]   (A = w planes, B = vT planes)
    bf16_gemm_kernel<true><<<dim3(1, 8, 16), blk, SMEM_GEMM>>>(
        (const uint16_t*)pwh, (const uint16_t*)pwl,
        (const uint16_t*)pvh, (const uint16_t*)pvl,
        out, Sq, Sq, Bsz * Sq, Dd,
        (long long)Sq * Sq, (long long)Sq, (long long)Sq * Dd);
}